// round 1
// baseline (speedup 1.0000x reference)
#include <cuda_runtime.h>
#include <math.h>

#define B_  32
#define T_  512
#define S_  64
#define D_  768
#define C_  8

// ---------------- scratch (static device globals; allocation-free) ----------
__device__ float g_x [B_*T_*D_];   // 48 MB  embedded input
__device__ float g_Qt[B_*T_*D_];   // 48 MB
__device__ float g_Vt[B_*T_*D_];   // 48 MB
__device__ float g_M [B_*S_*D_];   // 6 MB   memory slots
__device__ float g_Km[B_*S_*D_];   // 6 MB
__device__ float g_G [B_*S_*D_];   // 6 MB   gate pre-activation
__device__ float g_wr[B_*S_*D_];   // 6 MB   write
__device__ float g_W [B_*T_*S_];   // 4 MB   scores -> softmax weights (in place)
__device__ float g_cw[B_*S_];
__device__ float g_valid[B_];

// ---------------- small kernels ---------------------------------------------
__global__ void k_valid(const int* __restrict__ mask) {
    __shared__ int sh[512];
    int b = blockIdx.x, t = threadIdx.x;
    sh[t] = (mask[b*T_ + t] > 0) ? 1 : 0;
    __syncthreads();
    for (int o = 256; o > 0; o >>= 1) {
        if (t < o) sh[t] += sh[t + o];
        __syncthreads();
    }
    if (t == 0) g_valid[b] = (float)sh[0];
}

__global__ void k_embed(const int* __restrict__ ids,
                        const float* __restrict__ tok,
                        const float* __restrict__ pos) {
    int bt = blockIdx.x;                 // 0 .. B*T-1
    int t  = bt % T_;
    long id = ids[bt];
    const float4* te = (const float4*)(tok + id * (long)D_);
    const float4* pe = (const float4*)(pos + (long)t * D_);
    float4* xo = (float4*)(g_x + (long)bt * D_);
    int i = threadIdx.x;                 // 192 threads = 768/4
    float4 a = te[i], p4 = pe[i];
    a.x += p4.x; a.y += p4.y; a.z += p4.z; a.w += p4.w;
    xo[i] = a;
}

__global__ void k_minit(const float* __restrict__ mem) {
    int i = blockIdx.x * blockDim.x + threadIdx.x;
    if (i < B_*S_*D_) g_M[i] = mem[i % (S_*D_)];
}

// ---------------- generic tiled SGEMM (NN / NT / TN), optionally batched -----
// MODE 0 = NN: C[M,N] = A[M,K] * B[K,N]
// MODE 1 = NT: C[M,N] = A[M,K] * B[N,K]^T
// MODE 2 = TN: C[M,N] = A[K,M]^T * B[K,N]
template<int BM, int BN, int BK, int TM, int TN_, int MODE>
__global__ __launch_bounds__(256)
void gemm_kernel(const float* __restrict__ Ag, const float* __restrict__ Bg,
                 float* __restrict__ Cg, int M, int N, int K,
                 long long strideA, long long strideB, long long strideC)
{
    constexpr int THREADS = (BM/TM) * (BN/TN_);
    static_assert(THREADS == 256, "tile/thread mismatch");

    const float* A = Ag + (long long)blockIdx.z * strideA;
    const float* B = Bg + (long long)blockIdx.z * strideB;
    float*       C = Cg + (long long)blockIdx.z * strideC;

    __shared__ float As[BK][BM];
    __shared__ float Bs[BK][BN];

    const int tid  = threadIdx.x;
    const int tcol = tid % (BN/TN_);
    const int trow = tid / (BN/TN_);
    const int rowBase = blockIdx.y * BM;
    const int colBase = blockIdx.x * BN;

    float acc[TM][TN_];
#pragma unroll
    for (int i = 0; i < TM; i++)
#pragma unroll
        for (int j = 0; j < TN_; j++) acc[i][j] = 0.f;

    for (int k0 = 0; k0 < K; k0 += BK) {
        // ---- load A tile -> As[k][m]
        if (MODE == 0 || MODE == 1) {           // A row-major M x K
            constexpr int A4 = BM*BK/4;
#pragma unroll
            for (int e = tid; e < A4; e += THREADS) {
                int r  = e / (BK/4);
                int c4 = e % (BK/4);
                float4 v = *(const float4*)(A + (long long)(rowBase + r)*K + k0 + c4*4);
                As[c4*4+0][r] = v.x; As[c4*4+1][r] = v.y;
                As[c4*4+2][r] = v.z; As[c4*4+3][r] = v.w;
            }
        } else {                                // TN: A is K x M, lda = M
            constexpr int A4 = BM*BK/4;
#pragma unroll
            for (int e = tid; e < A4; e += THREADS) {
                int k  = e / (BM/4);
                int m4 = e % (BM/4);
                float4 v = *(const float4*)(A + (long long)(k0 + k)*M + rowBase + m4*4);
                *(float4*)&As[k][m4*4] = v;
            }
        }
        // ---- load B tile -> Bs[k][n]
        if (MODE == 0 || MODE == 2) {           // B row-major K x N
            constexpr int B4 = BK*BN/4;
#pragma unroll
            for (int e = tid; e < B4; e += THREADS) {
                int k  = e / (BN/4);
                int n4 = e % (BN/4);
                float4 v = *(const float4*)(B + (long long)(k0 + k)*N + colBase + n4*4);
                *(float4*)&Bs[k][n4*4] = v;
            }
        } else {                                // NT: B is N x K, ldb = K
            constexpr int B4 = BK*BN/4;
#pragma unroll
            for (int e = tid; e < B4; e += THREADS) {
                int n  = e / (BK/4);
                int k4 = e % (BK/4);
                float4 v = *(const float4*)(B + (long long)(colBase + n)*K + k0 + k4*4);
                Bs[k4*4+0][n] = v.x; Bs[k4*4+1][n] = v.y;
                Bs[k4*4+2][n] = v.z; Bs[k4*4+3][n] = v.w;
            }
        }
        __syncthreads();

#pragma unroll
        for (int kk = 0; kk < BK; kk++) {
            float a[TM], bb[TN_];
#pragma unroll
            for (int i = 0; i < TM; i++) a[i] = As[kk][trow*TM + i];
#pragma unroll
            for (int j = 0; j < TN_; j++) bb[j] = Bs[kk][tcol*TN_ + j];
#pragma unroll
            for (int i = 0; i < TM; i++)
#pragma unroll
                for (int j = 0; j < TN_; j++) acc[i][j] += a[i] * bb[j];
        }
        __syncthreads();
    }

#pragma unroll
    for (int i = 0; i < TM; i++) {
#pragma unroll
        for (int j = 0; j < TN_; j += 4) {
            float4 v = make_float4(acc[i][j], acc[i][j+1], acc[i][j+2], acc[i][j+3]);
            *(float4*)(C + (long long)(rowBase + trow*TM + i)*N + colBase + tcol*TN_ + j) = v;
        }
    }
}

// ---------------- softmax over S=64 slots, masked (in place on g_W) ----------
__global__ void k_softmax(const int* __restrict__ mask) {
    int wid  = (blockIdx.x * blockDim.x + threadIdx.x) >> 5;
    int lane = threadIdx.x & 31;
    if (wid >= B_*T_) return;
    int b = wid / T_, t = wid % T_;
    const float scale = 0.03608439182435161f;   // 1/sqrt(768)
    float* row = g_W + (size_t)wid * S_;
    float s0 = row[lane]      * scale;
    float s1 = row[lane + 32] * scale;
    s0 = fminf(fmaxf(s0, -20.f), 20.f);
    s1 = fminf(fmaxf(s1, -20.f), 20.f);
    float mx = fmaxf(s0, s1);
#pragma unroll
    for (int o = 16; o > 0; o >>= 1) mx = fmaxf(mx, __shfl_xor_sync(0xffffffffu, mx, o));
    float e0 = expf(s0 - mx), e1 = expf(s1 - mx);
    float sm = e0 + e1;
#pragma unroll
    for (int o = 16; o > 0; o >>= 1) sm += __shfl_xor_sync(0xffffffffu, sm, o);
    float inv = 1.f / sm;
    float mf  = (g_valid[b] > 0.f) ? ((mask[b*T_ + t] > 0) ? 1.f : 0.f) : 1.f;
    row[lane]      = e0 * inv * mf;
    row[lane + 32] = e1 * inv * mf;
}

// ---------------- memory update: M = clip(0.9 M + 0.1 sigmoid(G+b) * write) --
__global__ void k_update(const float* __restrict__ gate_b) {
    int i = blockIdx.x * blockDim.x + threadIdx.x;
    if (i >= B_*S_*D_) return;
    int d = i % D_;
    float gg  = g_G[i] + gate_b[d];
    float sig = 1.f / (1.f + expf(-gg));
    float v   = 0.9f * g_M[i] + 0.1f * (sig * g_wr[i]);
    g_M[i] = fminf(fmaxf(v, -50.f), 50.f);
}

// ---------------- column sum of masked W over T: cw[b,s] = sum_t m*W ---------
__global__ void k_colsum(const int* __restrict__ mask) {
    int b = blockIdx.x, s = threadIdx.x;
    const float* Wb = g_W + (size_t)b * T_ * S_;
    const int*   mb = mask + b * T_;
    float acc = 0.f;
    for (int t = 0; t < T_; t++)
        acc += (mb[t] > 0) ? Wb[t*S_ + s] : 0.f;
    g_cw[b*S_ + s] = acc;
}

// ---------------- pooled = cw^T M / nv; LayerNorm; logits --------------------
__global__ void k_final(const float* __restrict__ ln_g, const float* __restrict__ ln_b,
                        const float* __restrict__ cls_W, const float* __restrict__ cls_b,
                        float* __restrict__ out)
{
    __shared__ float cw[S_];
    __shared__ float p[D_];
    __shared__ float red[256];
    int b = blockIdx.x, tid = threadIdx.x;
    if (tid < S_) cw[tid] = g_cw[b*S_ + tid];
    __syncthreads();
    float invn = 1.f / fmaxf(g_valid[b], 1.f);
    for (int d = tid; d < D_; d += 256) {
        float acc = 0.f;
        const float* Mb = g_M + (size_t)b*S_*D_ + d;
#pragma unroll 8
        for (int s = 0; s < S_; s++) acc += cw[s] * Mb[s*D_];
        p[d] = acc * invn;
    }
    __syncthreads();
    // mean
    float ls = 0.f;
    for (int d = tid; d < D_; d += 256) ls += p[d];
    red[tid] = ls; __syncthreads();
    for (int o = 128; o > 0; o >>= 1) { if (tid < o) red[tid] += red[tid + o]; __syncthreads(); }
    float mu = red[0] / D_;
    __syncthreads();
    // variance
    float lv = 0.f;
    for (int d = tid; d < D_; d += 256) { float z = p[d] - mu; lv += z*z; }
    red[tid] = lv; __syncthreads();
    for (int o = 128; o > 0; o >>= 1) { if (tid < o) red[tid] += red[tid + o]; __syncthreads(); }
    float rs = rsqrtf(red[0] / D_ + 1e-5f);
    __syncthreads();
    for (int d = tid; d < D_; d += 256)
        p[d] = (p[d] - mu) * rs * ln_g[d] + ln_b[d];
    __syncthreads();
    // logits: warp w -> class w
    int w = tid >> 5, lane = tid & 31;
    float acc = 0.f;
    for (int d = lane; d < D_; d += 32) acc += p[d] * cls_W[d*C_ + w];
#pragma unroll
    for (int o = 16; o > 0; o >>= 1) acc += __shfl_down_sync(0xffffffffu, acc, o);
    if (lane == 0) {
        float v = acc + cls_b[w];
        if (!isfinite(v)) v = 0.f;
        out[b*C_ + w] = v;
    }
}

// ---------------- launch -----------------------------------------------------
extern "C" void kernel_launch(void* const* d_in, const int* in_sizes, int n_in,
                              void* d_out, int out_size)
{
    const int*   ids  = (const int*)  d_in[0];
    const int*   mask = (const int*)  d_in[1];
    const float* tok  = (const float*)d_in[2];
    const float* pos  = (const float*)d_in[3];
    const float* Wq   = (const float*)d_in[4];
    const float* Wk   = (const float*)d_in[5];
    const float* Wv   = (const float*)d_in[6];
    const float* gW   = (const float*)d_in[7];
    const float* gb   = (const float*)d_in[8];
    const float* lng  = (const float*)d_in[9];
    const float* lnb  = (const float*)d_in[10];
    const float* cW   = (const float*)d_in[11];
    const float* cb   = (const float*)d_in[12];
    const float* mem  = (const float*)d_in[13];
    float* out = (float*)d_out;

    float *px, *pQt, *pVt, *pM, *pKm, *pG, *pwr, *pW;
    cudaGetSymbolAddress((void**)&px,  g_x);
    cudaGetSymbolAddress((void**)&pQt, g_Qt);
    cudaGetSymbolAddress((void**)&pVt, g_Vt);
    cudaGetSymbolAddress((void**)&pM,  g_M);
    cudaGetSymbolAddress((void**)&pKm, g_Km);
    cudaGetSymbolAddress((void**)&pG,  g_G);
    cudaGetSymbolAddress((void**)&pwr, g_wr);
    cudaGetSymbolAddress((void**)&pW,  g_W);

    const long long sQ = (long long)T_*D_;   // Qt batch stride
    const long long sK = (long long)S_*D_;   // Km batch stride
    const long long sW = (long long)T_*S_;   // scores batch stride

    k_valid<<<B_, 512>>>(mask);
    k_embed<<<B_*T_, 192>>>(ids, tok, pos);
    k_minit<<<(B_*S_*D_ + 255)/256, 256>>>(mem);

    // Qt = x @ Wq ; Vt = x @ Wv
    gemm_kernel<128,64,16,8,4,0><<<dim3(D_/64, (B_*T_)/128, 1), 256>>>(px, Wq, pQt, B_*T_, D_, D_, 0,0,0);
    gemm_kernel<128,64,16,8,4,0><<<dim3(D_/64, (B_*T_)/128, 1), 256>>>(px, Wv, pVt, B_*T_, D_, D_, 0,0,0);

    for (int step = 0; step < 4; step++) {
        // Km = M @ Wk    (2048 x 768 @ 768 x 768)
        gemm_kernel<128,64,16,8,4,0><<<dim3(D_/64, (B_*S_)/128, 1), 256>>>(pM, Wk, pKm, B_*S_, D_, D_, 0,0,0);
        // scores[b] = Qt[b] @ Km[b]^T  (512 x 64, K=768)
        gemm_kernel<64,64,16,4,4,1><<<dim3(1, T_/64, B_), 256>>>(pQt, pKm, pW, T_, S_, D_, sQ, sK, sW);
        k_softmax<<<(B_*T_)/8, 256>>>(mask);
        // write[b] = W[b]^T @ Vt[b]  (64 x 768, K=512)
        gemm_kernel<64,64,16,4,4,2><<<dim3(D_/64, 1, B_), 256>>>(pW, pVt, pwr, S_, D_, T_, sW, sQ, sK);
        // G = M @ gate_W
        gemm_kernel<128,64,16,8,4,0><<<dim3(D_/64, (B_*S_)/128, 1), 256>>>(pM, gW, pG, B_*S_, D_, D_, 0,0,0);
        k_update<<<(B_*S_*D_ + 255)/256, 256>>>(gb);
    }

    // final attention read
    gemm_kernel<128,64,16,8,4,0><<<dim3(D_/64, (B_*S_)/128, 1), 256>>>(pM, Wk, pKm, B_*S_, D_, D_, 0,0,0);
    gemm_kernel<64,64,16,4,4,1><<<dim3(1, T_/64, B_), 256>>>(pQt, pKm, pW, T_, S_, D_, sQ, sK, sW);
    k_softmax<<<(B_*T_)/8, 256>>>(mask);
    k_colsum<<<B_, S_>>>(mask);
    k_final<<<B_, 256>>>(lng, lnb, cW, cb, out);
}

// round 3
// speedup vs baseline: 3.4128x; 3.4128x over previous
#include <cuda_runtime.h>
#include <cstdint>
#include <math.h>

#define B_  32
#define T_  512
#define S_  64
#define D_  768
#define C_  8

// ---------------- scratch (static device globals; allocation-free) ----------
__device__ float g_x [B_*T_*D_];
__device__ float g_Qt[B_*T_*D_];
__device__ float g_Vt[B_*T_*D_];
__device__ float g_M [B_*S_*D_];
__device__ float g_Km[B_*S_*D_];
__device__ float g_G [B_*S_*D_];
__device__ float g_wr[B_*S_*D_];
__device__ float g_W [B_*T_*S_];
__device__ float g_cw[B_*S_];
__device__ float g_valid[B_];

// ---------------- helpers ----------------------------------------------------
__device__ __forceinline__ float to_tf32(float f) {
    unsigned int u;
    asm("cvt.rna.tf32.f32 %0, %1;" : "=r"(u) : "f"(f));
    return __uint_as_float(u);
}

__device__ __forceinline__ void mma_tf32(float& c0, float& c1, float& c2, float& c3,
                                         float a0, float a1, float a2, float a3,
                                         float b0, float b1) {
    asm("mma.sync.aligned.m16n8k8.row.col.f32.tf32.tf32.f32 "
        "{%0,%1,%2,%3}, {%4,%5,%6,%7}, {%8,%9}, {%0,%1,%2,%3};"
        : "+f"(c0), "+f"(c1), "+f"(c2), "+f"(c3)
        : "r"(__float_as_uint(a0)), "r"(__float_as_uint(a1)),
          "r"(__float_as_uint(a2)), "r"(__float_as_uint(a3)),
          "r"(__float_as_uint(b0)), "r"(__float_as_uint(b1)));
}

// ---------------- small kernels ---------------------------------------------
__global__ void k_valid(const int* __restrict__ mask) {
    __shared__ int sh[512];
    int b = blockIdx.x, t = threadIdx.x;
    sh[t] = (mask[b*T_ + t] > 0) ? 1 : 0;
    __syncthreads();
    for (int o = 256; o > 0; o >>= 1) {
        if (t < o) sh[t] += sh[t + o];
        __syncthreads();
    }
    if (t == 0) g_valid[b] = (float)sh[0];
}

__global__ void k_embed(const int* __restrict__ ids,
                        const float* __restrict__ tok,
                        const float* __restrict__ pos) {
    int bt = blockIdx.x;
    int t  = bt % T_;
    long id = ids[bt];
    const float4* te = (const float4*)(tok + id * (long)D_);
    const float4* pe = (const float4*)(pos + (long)t * D_);
    float4* xo = (float4*)(g_x + (long)bt * D_);
    int i = threadIdx.x;
    float4 a = te[i], p4 = pe[i];
    a.x += p4.x; a.y += p4.y; a.z += p4.z; a.w += p4.w;
    xo[i] = a;
}

__global__ void k_minit(const float* __restrict__ mem) {
    int i = blockIdx.x * blockDim.x + threadIdx.x;
    if (i < B_*S_*D_) g_M[i] = mem[i % (S_*D_)];
}

// ---------------- tf32 tensor-core GEMM --------------------------------------
// MODE 0 = NN: C[M,N] = A[M,K] * B[K,N]        (A row-major, B row-major)
// MODE 1 = NT: C[M,N] = A[M,K] * Bg[N,K]^T     (B operand read as rows of Bg)
// MODE 2 = TN: C[M,N] = Ag[K,M]^T * B[K,N]     (A operand read as rows of Ag)
// BK = 32. smem tiles: As[32][BM+8] (k-major), Bs[32][BN+8] (k-major, holds B^T cols)
// swizzle: column index XOR ( 8 * ((k/4) & 3) )  -> conflict-free fragment reads.
template<int BM, int BN, int WM, int WN, int MODE>
__global__ __launch_bounds__((BM/WM)*(BN/WN)*32, 2)
void gemm_tc(const float* __restrict__ Ag, const float* __restrict__ Bg,
             float* __restrict__ Cg, int M, int N, int K,
             long long strideA, long long strideB, long long strideC)
{
    constexpr int BK = 32;
    constexpr int WARPS   = (BM/WM)*(BN/WN);
    constexpr int THREADS = WARPS*32;
    constexpr int MA = WM/16;     // m-atoms per warp
    constexpr int NA = WN/8;      // n-atoms per warp
    constexpr int LDA = BM + 8;
    constexpr int LDB = BN + 8;

    __shared__ float As[BK][LDA];
    __shared__ float Bs[BK][LDB];

    const float* A = Ag + (long long)blockIdx.z * strideA;
    const float* B = Bg + (long long)blockIdx.z * strideB;
    float*       C = Cg + (long long)blockIdx.z * strideC;

    const int tid    = threadIdx.x;
    const int warpId = tid >> 5;
    const int lane   = tid & 31;
    const int g      = lane >> 2;   // groupID 0..7
    const int tig    = lane & 3;    // thread-in-group 0..3

    const int warp_m = (warpId % (BM/WM)) * WM;
    const int warp_n = (warpId / (BM/WM)) * WN;
    const int rowBase = blockIdx.y * BM;
    const int colBase = blockIdx.x * BN;

    float acc[MA][NA][4];
#pragma unroll
    for (int i = 0; i < MA; i++)
#pragma unroll
        for (int j = 0; j < NA; j++) {
            acc[i][j][0]=0.f; acc[i][j][1]=0.f; acc[i][j][2]=0.f; acc[i][j][3]=0.f;
        }

    for (int k0 = 0; k0 < K; k0 += BK) {
        // ---------------- load A tile ----------------
        if (MODE == 0 || MODE == 1) {
            // A row-major [M,K]: read rows, scatter into k-major smem
            constexpr int TOT = BM * (BK/4);
#pragma unroll
            for (int idx = tid; idx < TOT; idx += THREADS) {
                int r  = idx >> 3;          // m-local
                int c4 = idx & 7;           // k-group of 4
                float4 v = *(const float4*)(A + (long long)(rowBase + r)*K + k0 + 4*c4);
                int col = r ^ (8*(c4 & 3));
                As[4*c4+0][col] = to_tf32(v.x);
                As[4*c4+1][col] = to_tf32(v.y);
                As[4*c4+2][col] = to_tf32(v.z);
                As[4*c4+3][col] = to_tf32(v.w);
            }
        } else {
            // TN: A operand is Ag[K,M] row-major (lda = M): rows are already k-major
            constexpr int TOT = BK * (BM/4);
#pragma unroll
            for (int idx = tid; idx < TOT; idx += THREADS) {
                int r  = idx / (BM/4);      // k-local
                int c4 = idx % (BM/4);      // m-group of 4
                float4 v = *(const float4*)(A + (long long)(k0 + r)*M + rowBase + 4*c4);
                int col = (4*c4) ^ (8*((r >> 2) & 3));
                As[r][col+0] = to_tf32(v.x);
                As[r][col+1] = to_tf32(v.y);
                As[r][col+2] = to_tf32(v.z);
                As[r][col+3] = to_tf32(v.w);
            }
        }
        // ---------------- load B tile ----------------
        if (MODE == 0 || MODE == 2) {
            // B row-major [K,N]
            constexpr int TOT = BK * (BN/4);
#pragma unroll
            for (int idx = tid; idx < TOT; idx += THREADS) {
                int r  = idx / (BN/4);      // k-local
                int c4 = idx % (BN/4);      // n-group of 4
                float4 v = *(const float4*)(B + (long long)(k0 + r)*N + colBase + 4*c4);
                int col = (4*c4) ^ (8*((r >> 2) & 3));
                Bs[r][col+0] = to_tf32(v.x);
                Bs[r][col+1] = to_tf32(v.y);
                Bs[r][col+2] = to_tf32(v.z);
                Bs[r][col+3] = to_tf32(v.w);
            }
        } else {
            // NT: B operand is Bg[N,K] row-major (ldb = K): rows are n, scatter over k
            constexpr int TOT = BN * (BK/4);
#pragma unroll
            for (int idx = tid; idx < TOT; idx += THREADS) {
                int r  = idx >> 3;          // n-local
                int c4 = idx & 7;           // k-group of 4
                float4 v = *(const float4*)(B + (long long)(colBase + r)*K + k0 + 4*c4);
                int col = r ^ (8*(c4 & 3));
                Bs[4*c4+0][col] = to_tf32(v.x);
                Bs[4*c4+1][col] = to_tf32(v.y);
                Bs[4*c4+2][col] = to_tf32(v.z);
                Bs[4*c4+3][col] = to_tf32(v.w);
            }
        }
        __syncthreads();

        // ---------------- compute: 4 k-steps of 8 ----------------
#pragma unroll
        for (int ks = 0; ks < 4; ks++) {
            const int kk   = 8*ks;
            const int swz0 = 8*((2*ks    ) & 3);
            const int swz1 = 8*((2*ks + 1) & 3);
            const float* ar0 = &As[kk + tig    ][0];
            const float* ar1 = &As[kk + tig + 4][0];
            const float* br0 = &Bs[kk + tig    ][0];
            const float* br1 = &Bs[kk + tig + 4][0];

            float a[MA][4];
#pragma unroll
            for (int ma = 0; ma < MA; ma++) {
                int mb = warp_m + 16*ma + g;
                a[ma][0] = ar0[(mb    ) ^ swz0];
                a[ma][1] = ar0[(mb + 8) ^ swz0];
                a[ma][2] = ar1[(mb    ) ^ swz1];
                a[ma][3] = ar1[(mb + 8) ^ swz1];
            }
            float bfr[NA][2];
#pragma unroll
            for (int na = 0; na < NA; na++) {
                int nb = warp_n + 8*na + g;
                bfr[na][0] = br0[nb ^ swz0];
                bfr[na][1] = br1[nb ^ swz1];
            }
#pragma unroll
            for (int ma = 0; ma < MA; ma++)
#pragma unroll
                for (int na = 0; na < NA; na++)
                    mma_tf32(acc[ma][na][0], acc[ma][na][1], acc[ma][na][2], acc[ma][na][3],
                             a[ma][0], a[ma][1], a[ma][2], a[ma][3],
                             bfr[na][0], bfr[na][1]);
        }
        __syncthreads();
    }

    // ---------------- epilogue ----------------
#pragma unroll
    for (int ma = 0; ma < MA; ma++) {
        int row0 = rowBase + warp_m + 16*ma + g;
        int row1 = row0 + 8;
#pragma unroll
        for (int na = 0; na < NA; na++) {
            int col = colBase + warp_n + 8*na + 2*tig;
            *(float2*)(C + (long long)row0*N + col) = make_float2(acc[ma][na][0], acc[ma][na][1]);
            *(float2*)(C + (long long)row1*N + col) = make_float2(acc[ma][na][2], acc[ma][na][3]);
        }
    }
}

// ---------------- softmax over S=64 slots, masked (in place on g_W) ----------
__global__ void k_softmax(const int* __restrict__ mask) {
    int wid  = (blockIdx.x * blockDim.x + threadIdx.x) >> 5;
    int lane = threadIdx.x & 31;
    if (wid >= B_*T_) return;
    int b = wid / T_, t = wid % T_;
    const float scale = 0.03608439182435161f;   // 1/sqrt(768)
    float* row = g_W + (size_t)wid * S_;
    float s0 = row[lane]      * scale;
    float s1 = row[lane + 32] * scale;
    s0 = fminf(fmaxf(s0, -20.f), 20.f);
    s1 = fminf(fmaxf(s1, -20.f), 20.f);
    float mx = fmaxf(s0, s1);
#pragma unroll
    for (int o = 16; o > 0; o >>= 1) mx = fmaxf(mx, __shfl_xor_sync(0xffffffffu, mx, o));
    float e0 = expf(s0 - mx), e1 = expf(s1 - mx);
    float sm = e0 + e1;
#pragma unroll
    for (int o = 16; o > 0; o >>= 1) sm += __shfl_xor_sync(0xffffffffu, sm, o);
    float inv = 1.f / sm;
    float mf  = (g_valid[b] > 0.f) ? ((mask[b*T_ + t] > 0) ? 1.f : 0.f) : 1.f;
    row[lane]      = e0 * inv * mf;
    row[lane + 32] = e1 * inv * mf;
}

// ---------------- memory update ----------------------------------------------
__global__ void k_update(const float* __restrict__ gate_b) {
    int i = blockIdx.x * blockDim.x + threadIdx.x;
    if (i >= B_*S_*D_) return;
    int d = i % D_;
    float gg  = g_G[i] + gate_b[d];
    float sig = 1.f / (1.f + expf(-gg));
    float v   = 0.9f * g_M[i] + 0.1f * (sig * g_wr[i]);
    g_M[i] = fminf(fmaxf(v, -50.f), 50.f);
}

// ---------------- column sum of masked W over T ------------------------------
__global__ void k_colsum(const int* __restrict__ mask) {
    int b = blockIdx.x, s = threadIdx.x;
    const float* Wb = g_W + (size_t)b * T_ * S_;
    const int*   mb = mask + b * T_;
    float acc = 0.f;
    for (int t = 0; t < T_; t++)
        acc += (mb[t] > 0) ? Wb[t*S_ + s] : 0.f;
    g_cw[b*S_ + s] = acc;
}

// ---------------- pooled; LayerNorm; logits ----------------------------------
__global__ void k_final(const float* __restrict__ ln_g, const float* __restrict__ ln_b,
                        const float* __restrict__ cls_W, const float* __restrict__ cls_b,
                        float* __restrict__ out)
{
    __shared__ float cw[S_];
    __shared__ float p[D_];
    __shared__ float red[256];
    int b = blockIdx.x, tid = threadIdx.x;
    if (tid < S_) cw[tid] = g_cw[b*S_ + tid];
    __syncthreads();
    float invn = 1.f / fmaxf(g_valid[b], 1.f);
    for (int d = tid; d < D_; d += 256) {
        float acc = 0.f;
        const float* Mb = g_M + (size_t)b*S_*D_ + d;
#pragma unroll 8
        for (int s = 0; s < S_; s++) acc += cw[s] * Mb[s*D_];
        p[d] = acc * invn;
    }
    __syncthreads();
    float ls = 0.f;
    for (int d = tid; d < D_; d += 256) ls += p[d];
    red[tid] = ls; __syncthreads();
    for (int o = 128; o > 0; o >>= 1) { if (tid < o) red[tid] += red[tid + o]; __syncthreads(); }
    float mu = red[0] / D_;
    __syncthreads();
    float lv = 0.f;
    for (int d = tid; d < D_; d += 256) { float z = p[d] - mu; lv += z*z; }
    red[tid] = lv; __syncthreads();
    for (int o = 128; o > 0; o >>= 1) { if (tid < o) red[tid] += red[tid + o]; __syncthreads(); }
    float rs = rsqrtf(red[0] / D_ + 1e-5f);
    __syncthreads();
    for (int d = tid; d < D_; d += 256)
        p[d] = (p[d] - mu) * rs * ln_g[d] + ln_b[d];
    __syncthreads();
    int w = tid >> 5, lane = tid & 31;
    float acc = 0.f;
    for (int d = lane; d < D_; d += 32) acc += p[d] * cls_W[d*C_ + w];
#pragma unroll
    for (int o = 16; o > 0; o >>= 1) acc += __shfl_down_sync(0xffffffffu, acc, o);
    if (lane == 0) {
        float v = acc + cls_b[w];
        if (!isfinite(v)) v = 0.f;
        out[b*C_ + w] = v;
    }
}

// ---------------- launch -----------------------------------------------------
extern "C" void kernel_launch(void* const* d_in, const int* in_sizes, int n_in,
                              void* d_out, int out_size)
{
    const int*   ids  = (const int*)  d_in[0];
    const int*   mask = (const int*)  d_in[1];
    const float* tok  = (const float*)d_in[2];
    const float* pos  = (const float*)d_in[3];
    const float* Wq   = (const float*)d_in[4];
    const float* Wk   = (const float*)d_in[5];
    const float* Wv   = (const float*)d_in[6];
    const float* gW   = (const float*)d_in[7];
    const float* gb   = (const float*)d_in[8];
    const float* lng  = (const float*)d_in[9];
    const float* lnb  = (const float*)d_in[10];
    const float* cW   = (const float*)d_in[11];
    const float* cb   = (const float*)d_in[12];
    const float* mem  = (const float*)d_in[13];
    float* out = (float*)d_out;

    float *px, *pQt, *pVt, *pM, *pKm, *pG, *pwr, *pW;
    cudaGetSymbolAddress((void**)&px,  g_x);
    cudaGetSymbolAddress((void**)&pQt, g_Qt);
    cudaGetSymbolAddress((void**)&pVt, g_Vt);
    cudaGetSymbolAddress((void**)&pM,  g_M);
    cudaGetSymbolAddress((void**)&pKm, g_Km);
    cudaGetSymbolAddress((void**)&pG,  g_G);
    cudaGetSymbolAddress((void**)&pwr, g_wr);
    cudaGetSymbolAddress((void**)&pW,  g_W);

    const long long sQ = (long long)T_*D_;
    const long long sK = (long long)S_*D_;
    const long long sW = (long long)T_*S_;

    k_valid<<<B_, 512>>>(mask);
    k_embed<<<B_*T_, 192>>>(ids, tok, pos);
    k_minit<<<(B_*S_*D_ + 255)/256, 256>>>(mem);

    // Qt = x @ Wq ; Vt = x @ Wv   (16384 x 768 x 768, NN)
    gemm_tc<128,128,64,32,0><<<dim3(D_/128, (B_*T_)/128, 1), 256>>>(px, Wq, pQt, B_*T_, D_, D_, 0,0,0);
    gemm_tc<128,128,64,32,0><<<dim3(D_/128, (B_*T_)/128, 1), 256>>>(px, Wv, pVt, B_*T_, D_, D_, 0,0,0);

    for (int step = 0; step < 4; step++) {
        // Km = M @ Wk   (2048 x 768 x 768, NN)
        gemm_tc<128,128,64,32,0><<<dim3(D_/128, (B_*S_)/128, 1), 256>>>(pM, Wk, pKm, B_*S_, D_, D_, 0,0,0);
        // scores[b] = Qt[b] @ Km[b]^T   (512 x 64, K=768, NT, batched)
        gemm_tc<64,64,32,32,1><<<dim3(1, T_/64, B_), 128>>>(pQt, pKm, pW, T_, S_, D_, sQ, sK, sW);
        k_softmax<<<(B_*T_)/8, 256>>>(mask);
        // write[b] = W[b]^T @ Vt[b]   (64 x 768, K=512, TN, batched)
        gemm_tc<64,128,32,32,2><<<dim3(D_/128, 1, B_), 256>>>(pW, pVt, pwr, S_, D_, T_, sW, sQ, sK);
        // G = M @ gate_W   (NN)
        gemm_tc<128,128,64,32,0><<<dim3(D_/128, (B_*S_)/128, 1), 256>>>(pM, gW, pG, B_*S_, D_, D_, 0,0,0);
        k_update<<<(B_*S_*D_ + 255)/256, 256>>>(gb);
    }

    // final attention read
    gemm_tc<128,128,64,32,0><<<dim3(D_/128, (B_*S_)/128, 1), 256>>>(pM, Wk, pKm, B_*S_, D_, D_, 0,0,0);
    gemm_tc<64,64,32,32,1><<<dim3(1, T_/64, B_), 128>>>(pQt, pKm, pW, T_, S_, D_, sQ, sK, sW);
    k_softmax<<<(B_*T_)/8, 256>>>(mask);
    k_colsum<<<B_, S_>>>(mask);
    k_final<<<B_, 256>>>(lng, lnb, cW, cb, out);
}

// round 4
// speedup vs baseline: 5.0884x; 1.4910x over previous
#include <cuda_runtime.h>
#include <cstdint>
#include <math.h>

#define B_  32
#define T_  512
#define S_  64
#define D_  768
#define C_  8
#define NG_ 1536   // packed Wk|gate_W width

// ---------------- scratch (static device globals; allocation-free) ----------
__device__ float g_x  [B_*T_*D_];
__device__ float g_Qt [B_*T_*D_];
__device__ float g_Vt [B_*T_*D_];
__device__ float g_M  [B_*S_*D_];
__device__ float g_KG [B_*S_*NG_];   // cols 0..767 = Km, 768..1535 = gate preact
__device__ float g_wr [B_*S_*D_];
__device__ float g_W  [B_*T_*S_];
__device__ float g_Wq [D_*D_];
__device__ float g_Wv [D_*D_];
__device__ float g_WkG[D_*NG_];
__device__ float g_cw [B_*S_];
__device__ float g_valid[B_];

// ---------------- helpers ----------------------------------------------------
__device__ __forceinline__ float to_tf32(float f) {
    unsigned int u;
    asm("cvt.rna.tf32.f32 %0, %1;" : "=r"(u) : "f"(f));
    return __uint_as_float(u);
}

__device__ __forceinline__ void mma_tf32(float& c0, float& c1, float& c2, float& c3,
                                         float a0, float a1, float a2, float a3,
                                         float b0, float b1) {
    asm("mma.sync.aligned.m16n8k8.row.col.f32.tf32.tf32.f32 "
        "{%0,%1,%2,%3}, {%4,%5,%6,%7}, {%8,%9}, {%0,%1,%2,%3};"
        : "+f"(c0), "+f"(c1), "+f"(c2), "+f"(c3)
        : "r"(__float_as_uint(a0)), "r"(__float_as_uint(a1)),
          "r"(__float_as_uint(a2)), "r"(__float_as_uint(a3)),
          "r"(__float_as_uint(b0)), "r"(__float_as_uint(b1)));
}

__device__ __forceinline__ void cp_async16(float* dst, const float* src) {
    unsigned u = (unsigned)__cvta_generic_to_shared(dst);
    asm volatile("cp.async.cg.shared.global [%0], [%1], 16;" :: "r"(u), "l"(src));
}

// ---------------- small kernels ---------------------------------------------
__global__ void k_valid(const int* __restrict__ mask) {
    __shared__ int sh[512];
    int b = blockIdx.x, t = threadIdx.x;
    sh[t] = (mask[b*T_ + t] > 0) ? 1 : 0;
    __syncthreads();
    for (int o = 256; o > 0; o >>= 1) {
        if (t < o) sh[t] += sh[t + o];
        __syncthreads();
    }
    if (t == 0) g_valid[b] = (float)sh[0];
}

__global__ void k_embed(const int* __restrict__ ids,
                        const float* __restrict__ tok,
                        const float* __restrict__ pos) {
    int bt = blockIdx.x;
    int t  = bt % T_;
    long id = ids[bt];
    const float4* te = (const float4*)(tok + id * (long)D_);
    const float4* pe = (const float4*)(pos + (long)t * D_);
    float4* xo = (float4*)(g_x + (long)bt * D_);
    int i = threadIdx.x;
    float4 a = te[i], p4 = pe[i];
    a.x = to_tf32(a.x + p4.x); a.y = to_tf32(a.y + p4.y);
    a.z = to_tf32(a.z + p4.z); a.w = to_tf32(a.w + p4.w);
    xo[i] = a;
}

__global__ void k_minit(const float* __restrict__ mem) {
    int i = blockIdx.x * blockDim.x + threadIdx.x;
    if (i < B_*S_*D_) g_M[i] = mem[i % (S_*D_)];
}

__global__ void k_round(const float* __restrict__ src, float* __restrict__ dst, int n) {
    int i = blockIdx.x * blockDim.x + threadIdx.x;
    if (i < n) dst[i] = to_tf32(src[i]);
}

__global__ void k_packKG(const float* __restrict__ Wk, const float* __restrict__ gW) {
    int i = blockIdx.x * blockDim.x + threadIdx.x;
    if (i >= D_*NG_) return;
    int k = i / NG_, j = i % NG_;
    float v = (j < D_) ? Wk[k*D_ + j] : gW[k*D_ + (j - D_)];
    g_WkG[i] = to_tf32(v);
}

// ---------------- tf32 tensor-core GEMM, cp.async double-buffered ------------
// MODE 0 = NN: C[M,N] = A[M,K](lda) * B[K,N](ldb)
// MODE 1 = NT: C[M,N] = A[M,K](lda) * Bg[N,K](ldb)^T
// MODE 2 = TN: C[M,N] = Ag[K,M](lda)^T * B[K,N](ldb)
// smem: m/n-major tiles have LD 36 (conflict-free 4g+tig); k-major LD = dim+8 (8tig+g).
template<int BM, int BN, int WM, int WN, int MODE, bool CVT_A>
__global__ void __launch_bounds__((BM/WM)*(BN/WN)*32, 2)
gemm_tc(const float* __restrict__ Ag, const float* __restrict__ Bg, float* __restrict__ Cg,
        int M, int N, int K, int lda, int ldb, int ldc,
        long long sA, long long sB, long long sC)
{
    constexpr int BK = 32;
    constexpr int WARPS   = (BM/WM)*(BN/WN);
    constexpr int THREADS = WARPS*32;
    constexpr int MA = WM/16;
    constexpr int NA = WN/8;
    constexpr int ALD   = (MODE==2) ? (BM+8) : 36;
    constexpr int AROWS = (MODE==2) ? BK : BM;
    constexpr int AE    = AROWS*ALD;
    constexpr int BLD   = (MODE==1) ? 36 : (BN+8);
    constexpr int BROWS = (MODE==1) ? BN : BK;
    constexpr int BE    = BROWS*BLD;

    extern __shared__ float smbuf[];
    float* Abuf = smbuf;
    float* Bbuf = smbuf + 2*AE;

    const float* A = Ag + (long long)blockIdx.z * sA;
    const float* B = Bg + (long long)blockIdx.z * sB;
    float*       C = Cg + (long long)blockIdx.z * sC;

    const int tid    = threadIdx.x;
    const int warpId = tid >> 5;
    const int lane   = tid & 31;
    const int g      = lane >> 2;
    const int tig    = lane & 3;
    const int warp_m = (warpId % (BM/WM)) * WM;
    const int warp_n = (warpId / (BM/WM)) * WN;
    const int rowBase = blockIdx.y * BM;
    const int colBase = blockIdx.x * BN;

    float acc[MA][NA][4];
#pragma unroll
    for (int i = 0; i < MA; i++)
#pragma unroll
        for (int j = 0; j < NA; j++) {
            acc[i][j][0]=0.f; acc[i][j][1]=0.f; acc[i][j][2]=0.f; acc[i][j][3]=0.f;
        }

    auto load_tile = [&](int kt, int s) {
        const int k0 = kt * BK;
        float* As = Abuf + s*AE;
        float* Bs = Bbuf + s*BE;
        if (MODE == 0 || MODE == 1) {
#pragma unroll
            for (int idx = tid; idx < BM*8; idx += THREADS) {
                int r = idx >> 3, c = idx & 7;
                cp_async16(As + r*ALD + 4*c, A + (long long)(rowBase + r)*lda + k0 + 4*c);
            }
        } else {
#pragma unroll
            for (int idx = tid; idx < BK*(BM/4); idx += THREADS) {
                int r = idx / (BM/4), c = idx % (BM/4);
                cp_async16(As + r*ALD + 4*c, A + (long long)(k0 + r)*lda + rowBase + 4*c);
            }
        }
        if (MODE == 1) {
#pragma unroll
            for (int idx = tid; idx < BN*8; idx += THREADS) {
                int r = idx >> 3, c = idx & 7;
                cp_async16(Bs + r*BLD + 4*c, B + (long long)(colBase + r)*ldb + k0 + 4*c);
            }
        } else {
#pragma unroll
            for (int idx = tid; idx < BK*(BN/4); idx += THREADS) {
                int r = idx / (BN/4), c = idx % (BN/4);
                cp_async16(Bs + r*BLD + 4*c, B + (long long)(k0 + r)*ldb + colBase + 4*c);
            }
        }
    };

    const int KT = K / BK;
    load_tile(0, 0);
    asm volatile("cp.async.commit_group;");

    for (int kt = 0; kt < KT; kt++) {
        const int cur = kt & 1;
        if (kt + 1 < KT) load_tile(kt + 1, cur ^ 1);
        asm volatile("cp.async.commit_group;");
        asm volatile("cp.async.wait_group 1;");
        __syncthreads();

        const float* As = Abuf + cur*AE;
        const float* Bs = Bbuf + cur*BE;

#pragma unroll
        for (int ks = 0; ks < 4; ks++) {
            const int kk = 8*ks;
            float a[MA][4], bf[NA][2];
            if (MODE == 2) {
                const float* r0 = As + (kk + tig    )*ALD;
                const float* r1 = As + (kk + tig + 4)*ALD;
#pragma unroll
                for (int ma = 0; ma < MA; ma++) {
                    int mb = warp_m + 16*ma + g;
                    a[ma][0] = r0[mb]; a[ma][1] = r0[mb+8];
                    a[ma][2] = r1[mb]; a[ma][3] = r1[mb+8];
                }
            } else {
#pragma unroll
                for (int ma = 0; ma < MA; ma++) {
                    int mb = warp_m + 16*ma + g;
                    const float* p0 = As + mb*ALD;
                    const float* p1 = As + (mb+8)*ALD;
                    a[ma][0] = p0[kk+tig];   a[ma][1] = p1[kk+tig];
                    a[ma][2] = p0[kk+tig+4]; a[ma][3] = p1[kk+tig+4];
                }
            }
            if (CVT_A) {
#pragma unroll
                for (int ma = 0; ma < MA; ma++)
#pragma unroll
                    for (int j = 0; j < 4; j++) a[ma][j] = to_tf32(a[ma][j]);
            }
            if (MODE == 1) {
#pragma unroll
                for (int na = 0; na < NA; na++) {
                    const float* p = Bs + (warp_n + 8*na + g)*BLD;
                    bf[na][0] = p[kk+tig]; bf[na][1] = p[kk+tig+4];
                }
            } else {
                const float* q0 = Bs + (kk + tig    )*BLD;
                const float* q1 = Bs + (kk + tig + 4)*BLD;
#pragma unroll
                for (int na = 0; na < NA; na++) {
                    int nb = warp_n + 8*na + g;
                    bf[na][0] = q0[nb]; bf[na][1] = q1[nb];
                }
            }
#pragma unroll
            for (int ma = 0; ma < MA; ma++)
#pragma unroll
                for (int na = 0; na < NA; na++)
                    mma_tf32(acc[ma][na][0], acc[ma][na][1], acc[ma][na][2], acc[ma][na][3],
                             a[ma][0], a[ma][1], a[ma][2], a[ma][3],
                             bf[na][0], bf[na][1]);
        }
        __syncthreads();
    }

    // epilogue: round to tf32 (all outputs feed either a GEMM or tolerant elementwise)
#pragma unroll
    for (int ma = 0; ma < MA; ma++) {
        int r0 = rowBase + warp_m + 16*ma + g;
        int r1 = r0 + 8;
#pragma unroll
        for (int na = 0; na < NA; na++) {
            int cc = colBase + warp_n + 8*na + 2*tig;
            *(float2*)(C + (long long)r0*ldc + cc) =
                make_float2(to_tf32(acc[ma][na][0]), to_tf32(acc[ma][na][1]));
            *(float2*)(C + (long long)r1*ldc + cc) =
                make_float2(to_tf32(acc[ma][na][2]), to_tf32(acc[ma][na][3]));
        }
    }
}

// ---------------- softmax over S=64 slots, masked (in place on g_W) ----------
__global__ void k_softmax(const int* __restrict__ mask) {
    int wid  = (blockIdx.x * blockDim.x + threadIdx.x) >> 5;
    int lane = threadIdx.x & 31;
    if (wid >= B_*T_) return;
    int b = wid / T_, t = wid % T_;
    const float scale = 0.03608439182435161f;   // 1/sqrt(768)
    float* row = g_W + (size_t)wid * S_;
    float s0 = row[lane]      * scale;
    float s1 = row[lane + 32] * scale;
    s0 = fminf(fmaxf(s0, -20.f), 20.f);
    s1 = fminf(fmaxf(s1, -20.f), 20.f);
    float mx = fmaxf(s0, s1);
#pragma unroll
    for (int o = 16; o > 0; o >>= 1) mx = fmaxf(mx, __shfl_xor_sync(0xffffffffu, mx, o));
    float e0 = expf(s0 - mx), e1 = expf(s1 - mx);
    float sm = e0 + e1;
#pragma unroll
    for (int o = 16; o > 0; o >>= 1) sm += __shfl_xor_sync(0xffffffffu, sm, o);
    float inv = 1.f / sm;
    float mf  = (g_valid[b] > 0.f) ? ((mask[b*T_ + t] > 0) ? 1.f : 0.f) : 1.f;
    row[lane]      = to_tf32(e0 * inv * mf);
    row[lane + 32] = to_tf32(e1 * inv * mf);
}

// ---------------- memory update (reads gate preact from g_KG) ----------------
__global__ void k_update(const float* __restrict__ gate_b) {
    int i = blockIdx.x * blockDim.x + threadIdx.x;
    if (i >= B_*S_*D_) return;
    int r = i / D_, d = i % D_;
    float gg  = g_KG[(size_t)r*NG_ + D_ + d] + gate_b[d];
    float sig = 1.f / (1.f + expf(-gg));
    float v   = 0.9f * g_M[i] + 0.1f * (sig * g_wr[i]);
    g_M[i] = fminf(fmaxf(v, -50.f), 50.f);
}

// ---------------- column sum of masked W over T ------------------------------
__global__ void k_colsum(const int* __restrict__ mask) {
    int b = blockIdx.x, s = threadIdx.x;
    const float* Wb = g_W + (size_t)b * T_ * S_;
    const int*   mb = mask + b * T_;
    float acc = 0.f;
    for (int t = 0; t < T_; t++)
        acc += (mb[t] > 0) ? Wb[t*S_ + s] : 0.f;
    g_cw[b*S_ + s] = acc;
}

// ---------------- pooled; LayerNorm; logits ----------------------------------
__global__ void k_final(const float* __restrict__ ln_g, const float* __restrict__ ln_b,
                        const float* __restrict__ cls_W, const float* __restrict__ cls_b,
                        float* __restrict__ out)
{
    __shared__ float cw[S_];
    __shared__ float p[D_];
    __shared__ float red[256];
    int b = blockIdx.x, tid = threadIdx.x;
    if (tid < S_) cw[tid] = g_cw[b*S_ + tid];
    __syncthreads();
    float invn = 1.f / fmaxf(g_valid[b], 1.f);
    for (int d = tid; d < D_; d += 256) {
        float acc = 0.f;
        const float* Mb = g_M + (size_t)b*S_*D_ + d;
#pragma unroll 8
        for (int s = 0; s < S_; s++) acc += cw[s] * Mb[s*D_];
        p[d] = acc * invn;
    }
    __syncthreads();
    float ls = 0.f;
    for (int d = tid; d < D_; d += 256) ls += p[d];
    red[tid] = ls; __syncthreads();
    for (int o = 128; o > 0; o >>= 1) { if (tid < o) red[tid] += red[tid + o]; __syncthreads(); }
    float mu = red[0] / D_;
    __syncthreads();
    float lv = 0.f;
    for (int d = tid; d < D_; d += 256) { float z = p[d] - mu; lv += z*z; }
    red[tid] = lv; __syncthreads();
    for (int o = 128; o > 0; o >>= 1) { if (tid < o) red[tid] += red[tid + o]; __syncthreads(); }
    float rs = rsqrtf(red[0] / D_ + 1e-5f);
    __syncthreads();
    for (int d = tid; d < D_; d += 256)
        p[d] = (p[d] - mu) * rs * ln_g[d] + ln_b[d];
    __syncthreads();
    int w = tid >> 5, lane = tid & 31;
    float acc = 0.f;
    for (int d = lane; d < D_; d += 32) acc += p[d] * cls_W[d*C_ + w];
#pragma unroll
    for (int o = 16; o > 0; o >>= 1) acc += __shfl_down_sync(0xffffffffu, acc, o);
    if (lane == 0) {
        float v = acc + cls_b[w];
        if (!isfinite(v)) v = 0.f;
        out[b*C_ + w] = v;
    }
}

// ---------------- launch -----------------------------------------------------
extern "C" void kernel_launch(void* const* d_in, const int* in_sizes, int n_in,
                              void* d_out, int out_size)
{
    const int*   ids  = (const int*)  d_in[0];
    const int*   mask = (const int*)  d_in[1];
    const float* tok  = (const float*)d_in[2];
    const float* pos  = (const float*)d_in[3];
    const float* Wq   = (const float*)d_in[4];
    const float* Wk   = (const float*)d_in[5];
    const float* Wv   = (const float*)d_in[6];
    const float* gW   = (const float*)d_in[7];
    const float* gb   = (const float*)d_in[8];
    const float* lng  = (const float*)d_in[9];
    const float* lnb  = (const float*)d_in[10];
    const float* cW   = (const float*)d_in[11];
    const float* cb   = (const float*)d_in[12];
    const float* mem  = (const float*)d_in[13];
    float* out = (float*)d_out;

    float *px, *pQt, *pVt, *pM, *pKG, *pwr, *pW, *pWq, *pWv, *pWkG;
    cudaGetSymbolAddress((void**)&px,   g_x);
    cudaGetSymbolAddress((void**)&pQt,  g_Qt);
    cudaGetSymbolAddress((void**)&pVt,  g_Vt);
    cudaGetSymbolAddress((void**)&pM,   g_M);
    cudaGetSymbolAddress((void**)&pKG,  g_KG);
    cudaGetSymbolAddress((void**)&pwr,  g_wr);
    cudaGetSymbolAddress((void**)&pW,   g_W);
    cudaGetSymbolAddress((void**)&pWq,  g_Wq);
    cudaGetSymbolAddress((void**)&pWv,  g_Wv);
    cudaGetSymbolAddress((void**)&pWkG, g_WkG);

    // dynamic smem sizes per instantiation
    const int SM_NN = 2*(128*36 + 32*136)*4;   // 71680
    const int SM_NT = 2*(64*36  + 64*36 )*4;   // 36864
    const int SM_TN = 2*(32*72  + 32*136)*4;   // 53248

    cudaFuncSetAttribute(gemm_tc<128,128,64,32,0,false>, cudaFuncAttributeMaxDynamicSharedMemorySize, SM_NN);
    cudaFuncSetAttribute(gemm_tc<128,128,64,32,0,true >, cudaFuncAttributeMaxDynamicSharedMemorySize, SM_NN);
    cudaFuncSetAttribute(gemm_tc<64,64,32,32,1,false  >, cudaFuncAttributeMaxDynamicSharedMemorySize, SM_NT);
    cudaFuncSetAttribute(gemm_tc<64,128,32,32,2,false >, cudaFuncAttributeMaxDynamicSharedMemorySize, SM_TN);

    const long long sQ = (long long)T_*D_;
    const long long sK = (long long)S_*NG_;
    const long long sWb= (long long)T_*S_;
    const long long sV = (long long)T_*D_;
    const long long swr= (long long)S_*D_;

    k_valid<<<B_, 512>>>(mask);
    k_embed<<<B_*T_, 192>>>(ids, tok, pos);
    k_minit<<<(B_*S_*D_ + 255)/256, 256>>>(mem);
    k_round<<<(D_*D_ + 255)/256, 256>>>(Wq, pWq, D_*D_);
    k_round<<<(D_*D_ + 255)/256, 256>>>(Wv, pWv, D_*D_);
    k_packKG<<<(D_*NG_ + 255)/256, 256>>>(Wk, gW);

    // Qt = x @ Wq ; Vt = x @ Wv   (16384 x 768 x 768)
    gemm_tc<128,128,64,32,0,false><<<dim3(D_/128, (B_*T_)/128, 1), 256, SM_NN>>>(
        px, pWq, pQt, B_*T_, D_, D_, D_, D_, D_, 0,0,0);
    gemm_tc<128,128,64,32,0,false><<<dim3(D_/128, (B_*T_)/128, 1), 256, SM_NN>>>(
        px, pWv, pVt, B_*T_, D_, D_, D_, D_, D_, 0,0,0);

    for (int step = 0; step < 4; step++) {
        // [Km | G] = M @ [Wk | gate_W]   (2048 x 1536 x 768)
        gemm_tc<128,128,64,32,0,true><<<dim3(NG_/128, (B_*S_)/128, 1), 256, SM_NN>>>(
            pM, pWkG, pKG, B_*S_, NG_, D_, D_, NG_, NG_, 0,0,0);
        // scores[b] = Qt[b] @ Km[b]^T   (512 x 64, K=768)
        gemm_tc<64,64,32,32,1,false><<<dim3(1, T_/64, B_), 128, SM_NT>>>(
            pQt, pKG, pW, T_, S_, D_, D_, NG_, S_, sQ, sK, sWb);
        k_softmax<<<(B_*T_)/8, 256>>>(mask);
        // write[b] = W[b]^T @ Vt[b]   (64 x 768, K=512)
        gemm_tc<64,128,32,32,2,false><<<dim3(D_/128, 1, B_), 256, SM_TN>>>(
            pW, pVt, pwr, S_, D_, T_, S_, D_, D_, sWb, sV, swr);
        k_update<<<(B_*S_*D_ + 255)/256, 256>>>(gb);
    }

    // final read: Km only (N = 768 columns of the packed weight)
    gemm_tc<128,128,64,32,0,true><<<dim3(D_/128, (B_*S_)/128, 1), 256, SM_NN>>>(
        pM, pWkG, pKG, B_*S_, D_, D_, D_, NG_, NG_, 0,0,0);
    gemm_tc<64,64,32,32,1,false><<<dim3(1, T_/64, B_), 128, SM_NT>>>(
        pQt, pKG, pW, T_, S_, D_, D_, NG_, S_, sQ, sK, sWb);
    k_softmax<<<(B_*T_)/8, 256>>>(mask);
    k_colsum<<<B_, S_>>>(mask);
    k_final<<<B_, 256>>>(lng, lnb, cW, cb, out);
}

// round 5
// speedup vs baseline: 6.0118x; 1.1815x over previous
#include <cuda_runtime.h>
#include <cstdint>
#include <math.h>

#define B_  32
#define T_  512
#define S_  64
#define D_  768
#define C_  8
#define NW_ 1536   // packed [Wqk | Wv] width

// ---------------- scratch (static device globals; allocation-free) ----------
__device__ float g_x  [B_*T_*D_];    // embedded input, tf32-rounded
__device__ float g_QV [B_*T_*NW_];   // cols 0..767 = Qk, 768..1535 = Vt
__device__ float g_M  [B_*S_*D_];    // fp32 memory state
__device__ float g_G  [B_*S_*D_];    // gate preact
__device__ float g_W  [B_*T_*S_];    // scores -> softmax weights
__device__ float g_Wp [D_*NW_];      // packed [Wqk | Wv], tf32
__device__ float g_gWr[D_*D_];       // gate_W, tf32
__device__ float g_cw [B_*S_];
__device__ float g_valid[B_];

// ---------------- helpers ----------------------------------------------------
__device__ __forceinline__ float to_tf32(float f) {
    unsigned int u;
    asm("cvt.rna.tf32.f32 %0, %1;" : "=r"(u) : "f"(f));
    return __uint_as_float(u);
}

__device__ __forceinline__ void mma_tf32(float& c0, float& c1, float& c2, float& c3,
                                         float a0, float a1, float a2, float a3,
                                         float b0, float b1) {
    asm("mma.sync.aligned.m16n8k8.row.col.f32.tf32.tf32.f32 "
        "{%0,%1,%2,%3}, {%4,%5,%6,%7}, {%8,%9}, {%0,%1,%2,%3};"
        : "+f"(c0), "+f"(c1), "+f"(c2), "+f"(c3)
        : "r"(__float_as_uint(a0)), "r"(__float_as_uint(a1)),
          "r"(__float_as_uint(a2)), "r"(__float_as_uint(a3)),
          "r"(__float_as_uint(b0)), "r"(__float_as_uint(b1)));
}

__device__ __forceinline__ void cp_async16(float* dst, const float* src) {
    unsigned u = (unsigned)__cvta_generic_to_shared(dst);
    asm volatile("cp.async.cg.shared.global [%0], [%1], 16;" :: "r"(u), "l"(src));
}

// ---------------- small kernels ---------------------------------------------
__global__ void k_valid(const int* __restrict__ mask) {
    __shared__ int sh[512];
    int b = blockIdx.x, t = threadIdx.x;
    sh[t] = (mask[b*T_ + t] > 0) ? 1 : 0;
    __syncthreads();
    for (int o = 256; o > 0; o >>= 1) {
        if (t < o) sh[t] += sh[t + o];
        __syncthreads();
    }
    if (t == 0) g_valid[b] = (float)sh[0];
}

__global__ void k_embed(const int* __restrict__ ids,
                        const float* __restrict__ tok,
                        const float* __restrict__ pos) {
    int bt = blockIdx.x;
    int t  = bt % T_;
    long id = ids[bt];
    const float4* te = (const float4*)(tok + id * (long)D_);
    const float4* pe = (const float4*)(pos + (long)t * D_);
    float4* xo = (float4*)(g_x + (long)bt * D_);
    int i = threadIdx.x;
    float4 a = te[i], p4 = pe[i];
    a.x = to_tf32(a.x + p4.x); a.y = to_tf32(a.y + p4.y);
    a.z = to_tf32(a.z + p4.z); a.w = to_tf32(a.w + p4.w);
    xo[i] = a;
}

__global__ void k_minit(const float* __restrict__ mem) {
    int i = blockIdx.x * blockDim.x + threadIdx.x;
    if (i < B_*S_*D_) g_M[i] = mem[i % (S_*D_)];
}

__global__ void k_round(const float* __restrict__ src, float* __restrict__ dst, int n) {
    int i = blockIdx.x * blockDim.x + threadIdx.x;
    if (i < n) dst[i] = to_tf32(src[i]);
}

__global__ void k_packWv(const float* __restrict__ Wv) {
    int i = blockIdx.x * blockDim.x + threadIdx.x;
    if (i >= D_*D_) return;
    int k = i / D_, j = i % D_;
    g_Wp[(size_t)k*NW_ + D_ + j] = to_tf32(Wv[i]);
}

// ---------------- tf32 tensor-core GEMM, cp.async double-buffered ------------
// MODE 0 = NN: C[M,N] = A[M,K](lda) * B[K,N](ldb)
// MODE 1 = NT: C[M,N] = A[M,K](lda) * Bg[N,K](ldb)^T
// MODE 2 = TN: C[M,N] = Ag[K,M](lda)^T * B[K,N](ldb)
// EPI 0 = store to_tf32 ; EPI 1 = fused memory update (C = M state, Gp = gate)
template<int BM, int BN, int WM, int WN, int MODE, bool CVT_A, bool CVT_B, int EPI>
__global__ void __launch_bounds__((BM/WM)*(BN/WN)*32, 2)
gemm_tc(const float* __restrict__ Ag, const float* __restrict__ Bg, float* __restrict__ Cg,
        const float* __restrict__ Gp, const float* __restrict__ gbp,
        int M, int N, int K, int lda, int ldb, int ldc,
        long long sA, long long sB, long long sC)
{
    constexpr int BK = 32;
    constexpr int WARPS   = (BM/WM)*(BN/WN);
    constexpr int THREADS = WARPS*32;
    constexpr int MA = WM/16;
    constexpr int NA = WN/8;
    constexpr int ALD   = (MODE==2) ? (BM+8) : 36;
    constexpr int AROWS = (MODE==2) ? BK : BM;
    constexpr int AE    = AROWS*ALD;
    constexpr int BLD   = (MODE==1) ? 36 : (BN+8);
    constexpr int BROWS = (MODE==1) ? BN : BK;
    constexpr int BE    = BROWS*BLD;

    extern __shared__ float smbuf[];
    float* Abuf = smbuf;
    float* Bbuf = smbuf + 2*AE;

    const float* A = Ag + (long long)blockIdx.z * sA;
    const float* B = Bg + (long long)blockIdx.z * sB;
    float*       C = Cg + (long long)blockIdx.z * sC;

    const int tid    = threadIdx.x;
    const int warpId = tid >> 5;
    const int lane   = tid & 31;
    const int g      = lane >> 2;
    const int tig    = lane & 3;
    const int warp_m = (warpId % (BM/WM)) * WM;
    const int warp_n = (warpId / (BM/WM)) * WN;
    const int rowBase = blockIdx.y * BM;
    const int colBase = blockIdx.x * BN;

    float acc[MA][NA][4];
#pragma unroll
    for (int i = 0; i < MA; i++)
#pragma unroll
        for (int j = 0; j < NA; j++) {
            acc[i][j][0]=0.f; acc[i][j][1]=0.f; acc[i][j][2]=0.f; acc[i][j][3]=0.f;
        }

    auto load_tile = [&](int kt, int s) {
        const int k0 = kt * BK;
        float* As = Abuf + s*AE;
        float* Bs = Bbuf + s*BE;
        if (MODE == 0 || MODE == 1) {
#pragma unroll
            for (int idx = tid; idx < BM*8; idx += THREADS) {
                int r = idx >> 3, c = idx & 7;
                cp_async16(As + r*ALD + 4*c, A + (long long)(rowBase + r)*lda + k0 + 4*c);
            }
        } else {
#pragma unroll
            for (int idx = tid; idx < BK*(BM/4); idx += THREADS) {
                int r = idx / (BM/4), c = idx % (BM/4);
                cp_async16(As + r*ALD + 4*c, A + (long long)(k0 + r)*lda + rowBase + 4*c);
            }
        }
        if (MODE == 1) {
#pragma unroll
            for (int idx = tid; idx < BN*8; idx += THREADS) {
                int r = idx >> 3, c = idx & 7;
                cp_async16(Bs + r*BLD + 4*c, B + (long long)(colBase + r)*ldb + k0 + 4*c);
            }
        } else {
#pragma unroll
            for (int idx = tid; idx < BK*(BN/4); idx += THREADS) {
                int r = idx / (BN/4), c = idx % (BN/4);
                cp_async16(Bs + r*BLD + 4*c, B + (long long)(k0 + r)*ldb + colBase + 4*c);
            }
        }
    };

    const int KT = K / BK;
    load_tile(0, 0);
    asm volatile("cp.async.commit_group;");

    for (int kt = 0; kt < KT; kt++) {
        const int cur = kt & 1;
        if (kt + 1 < KT) load_tile(kt + 1, cur ^ 1);
        asm volatile("cp.async.commit_group;");
        asm volatile("cp.async.wait_group 1;");
        __syncthreads();

        const float* As = Abuf + cur*AE;
        const float* Bs = Bbuf + cur*BE;

#pragma unroll
        for (int ks = 0; ks < 4; ks++) {
            const int kk = 8*ks;
            float a[MA][4], bf[NA][2];
            if (MODE == 2) {
                const float* r0 = As + (kk + tig    )*ALD;
                const float* r1 = As + (kk + tig + 4)*ALD;
#pragma unroll
                for (int ma = 0; ma < MA; ma++) {
                    int mb = warp_m + 16*ma + g;
                    a[ma][0] = r0[mb]; a[ma][1] = r0[mb+8];
                    a[ma][2] = r1[mb]; a[ma][3] = r1[mb+8];
                }
            } else {
#pragma unroll
                for (int ma = 0; ma < MA; ma++) {
                    int mb = warp_m + 16*ma + g;
                    const float* p0 = As + mb*ALD;
                    const float* p1 = As + (mb+8)*ALD;
                    a[ma][0] = p0[kk+tig];   a[ma][1] = p1[kk+tig];
                    a[ma][2] = p0[kk+tig+4]; a[ma][3] = p1[kk+tig+4];
                }
            }
            if (CVT_A) {
#pragma unroll
                for (int ma = 0; ma < MA; ma++)
#pragma unroll
                    for (int j = 0; j < 4; j++) a[ma][j] = to_tf32(a[ma][j]);
            }
            if (MODE == 1) {
#pragma unroll
                for (int na = 0; na < NA; na++) {
                    const float* p = Bs + (warp_n + 8*na + g)*BLD;
                    bf[na][0] = p[kk+tig]; bf[na][1] = p[kk+tig+4];
                }
            } else {
                const float* q0 = Bs + (kk + tig    )*BLD;
                const float* q1 = Bs + (kk + tig + 4)*BLD;
#pragma unroll
                for (int na = 0; na < NA; na++) {
                    int nb = warp_n + 8*na + g;
                    bf[na][0] = q0[nb]; bf[na][1] = q1[nb];
                }
            }
            if (CVT_B) {
#pragma unroll
                for (int na = 0; na < NA; na++) {
                    bf[na][0] = to_tf32(bf[na][0]);
                    bf[na][1] = to_tf32(bf[na][1]);
                }
            }
#pragma unroll
            for (int ma = 0; ma < MA; ma++)
#pragma unroll
                for (int na = 0; na < NA; na++)
                    mma_tf32(acc[ma][na][0], acc[ma][na][1], acc[ma][na][2], acc[ma][na][3],
                             a[ma][0], a[ma][1], a[ma][2], a[ma][3],
                             bf[na][0], bf[na][1]);
        }
        __syncthreads();
    }

    if (EPI == 0) {
#pragma unroll
        for (int ma = 0; ma < MA; ma++) {
            int r0 = rowBase + warp_m + 16*ma + g;
            int r1 = r0 + 8;
#pragma unroll
            for (int na = 0; na < NA; na++) {
                int cc = colBase + warp_n + 8*na + 2*tig;
                *(float2*)(C + (long long)r0*ldc + cc) =
                    make_float2(to_tf32(acc[ma][na][0]), to_tf32(acc[ma][na][1]));
                *(float2*)(C + (long long)r1*ldc + cc) =
                    make_float2(to_tf32(acc[ma][na][2]), to_tf32(acc[ma][na][3]));
            }
        }
    } else {
        // fused memory update: C holds fp32 M state; acc = write[s,d]
        const float* G = Gp + (long long)blockIdx.z * sC;
#pragma unroll
        for (int ma = 0; ma < MA; ma++) {
            int r0 = rowBase + warp_m + 16*ma + g;
            int r1 = r0 + 8;
#pragma unroll
            for (int na = 0; na < NA; na++) {
                int cc = colBase + warp_n + 8*na + 2*tig;
                float gb0 = gbp[cc], gb1 = gbp[cc+1];
#pragma unroll
                for (int rr = 0; rr < 2; rr++) {
                    int   row = rr ? r1 : r0;
                    float w0  = acc[ma][na][2*rr], w1 = acc[ma][na][2*rr+1];
                    float2 mo = *(float2*)(C + (long long)row*ldc + cc);
                    float2 go = *(float2*)(G + (long long)row*ldc + cc);
                    float s0 = 1.f / (1.f + expf(-(go.x + gb0)));
                    float s1 = 1.f / (1.f + expf(-(go.y + gb1)));
                    float n0 = fminf(fmaxf(0.9f*mo.x + 0.1f*s0*w0, -50.f), 50.f);
                    float n1 = fminf(fmaxf(0.9f*mo.y + 0.1f*s1*w1, -50.f), 50.f);
                    *(float2*)(C + (long long)row*ldc + cc) = make_float2(n0, n1);
                }
            }
        }
    }
}

// ---------------- softmax over S=64 slots, masked (in place on g_W) ----------
__global__ void k_softmax(const int* __restrict__ mask) {
    int wid  = (blockIdx.x * blockDim.x + threadIdx.x) >> 5;
    int lane = threadIdx.x & 31;
    if (wid >= B_*T_) return;
    int b = wid / T_, t = wid % T_;
    const float scale = 0.03608439182435161f;   // 1/sqrt(768)
    float* row = g_W + (size_t)wid * S_;
    float s0 = row[lane]      * scale;
    float s1 = row[lane + 32] * scale;
    s0 = fminf(fmaxf(s0, -20.f), 20.f);
    s1 = fminf(fmaxf(s1, -20.f), 20.f);
    float mx = fmaxf(s0, s1);
#pragma unroll
    for (int o = 16; o > 0; o >>= 1) mx = fmaxf(mx, __shfl_xor_sync(0xffffffffu, mx, o));
    float e0 = expf(s0 - mx), e1 = expf(s1 - mx);
    float sm = e0 + e1;
#pragma unroll
    for (int o = 16; o > 0; o >>= 1) sm += __shfl_xor_sync(0xffffffffu, sm, o);
    float inv = 1.f / sm;
    float mf  = (g_valid[b] > 0.f) ? ((mask[b*T_ + t] > 0) ? 1.f : 0.f) : 1.f;
    row[lane]      = to_tf32(e0 * inv * mf);
    row[lane + 32] = to_tf32(e1 * inv * mf);
}

// ---------------- column sum of masked W over T ------------------------------
__global__ void k_colsum(const int* __restrict__ mask) {
    int b = blockIdx.x, s = threadIdx.x;
    const float* Wb = g_W + (size_t)b * T_ * S_;
    const int*   mb = mask + b * T_;
    float acc = 0.f;
    for (int t = 0; t < T_; t++)
        acc += (mb[t] > 0) ? Wb[t*S_ + s] : 0.f;
    g_cw[b*S_ + s] = acc;
}

// ---------------- pooled; LayerNorm; logits ----------------------------------
__global__ void k_final(const float* __restrict__ ln_g, const float* __restrict__ ln_b,
                        const float* __restrict__ cls_W, const float* __restrict__ cls_b,
                        float* __restrict__ out)
{
    __shared__ float cw[S_];
    __shared__ float p[D_];
    __shared__ float red[256];
    int b = blockIdx.x, tid = threadIdx.x;
    if (tid < S_) cw[tid] = g_cw[b*S_ + tid];
    __syncthreads();
    float invn = 1.f / fmaxf(g_valid[b], 1.f);
    for (int d = tid; d < D_; d += 256) {
        float acc = 0.f;
        const float* Mb = g_M + (size_t)b*S_*D_ + d;
#pragma unroll 8
        for (int s = 0; s < S_; s++) acc += cw[s] * Mb[s*D_];
        p[d] = acc * invn;
    }
    __syncthreads();
    float ls = 0.f;
    for (int d = tid; d < D_; d += 256) ls += p[d];
    red[tid] = ls; __syncthreads();
    for (int o = 128; o > 0; o >>= 1) { if (tid < o) red[tid] += red[tid + o]; __syncthreads(); }
    float mu = red[0] / D_;
    __syncthreads();
    float lv = 0.f;
    for (int d = tid; d < D_; d += 256) { float z = p[d] - mu; lv += z*z; }
    red[tid] = lv; __syncthreads();
    for (int o = 128; o > 0; o >>= 1) { if (tid < o) red[tid] += red[tid + o]; __syncthreads(); }
    float rs = rsqrtf(red[0] / D_ + 1e-5f);
    __syncthreads();
    for (int d = tid; d < D_; d += 256)
        p[d] = (p[d] - mu) * rs * ln_g[d] + ln_b[d];
    __syncthreads();
    int w = tid >> 5, lane = tid & 31;
    float acc = 0.f;
    for (int d = lane; d < D_; d += 32) acc += p[d] * cls_W[d*C_ + w];
#pragma unroll
    for (int o = 16; o > 0; o >>= 1) acc += __shfl_down_sync(0xffffffffu, acc, o);
    if (lane == 0) {
        float v = acc + cls_b[w];
        if (!isfinite(v)) v = 0.f;
        out[b*C_ + w] = v;
    }
}

// ---------------- launch -----------------------------------------------------
extern "C" void kernel_launch(void* const* d_in, const int* in_sizes, int n_in,
                              void* d_out, int out_size)
{
    const int*   ids  = (const int*)  d_in[0];
    const int*   mask = (const int*)  d_in[1];
    const float* tok  = (const float*)d_in[2];
    const float* pos  = (const float*)d_in[3];
    const float* Wq   = (const float*)d_in[4];
    const float* Wk   = (const float*)d_in[5];
    const float* Wv   = (const float*)d_in[6];
    const float* gW   = (const float*)d_in[7];
    const float* gb   = (const float*)d_in[8];
    const float* lng  = (const float*)d_in[9];
    const float* lnb  = (const float*)d_in[10];
    const float* cW   = (const float*)d_in[11];
    const float* cb   = (const float*)d_in[12];
    const float* mem  = (const float*)d_in[13];
    float* out = (float*)d_out;

    float *px, *pQV, *pM, *pG, *pW, *pWp, *pgWr;
    cudaGetSymbolAddress((void**)&px,   g_x);
    cudaGetSymbolAddress((void**)&pQV,  g_QV);
    cudaGetSymbolAddress((void**)&pM,   g_M);
    cudaGetSymbolAddress((void**)&pG,   g_G);
    cudaGetSymbolAddress((void**)&pW,   g_W);
    cudaGetSymbolAddress((void**)&pWp,  g_Wp);
    cudaGetSymbolAddress((void**)&pgWr, g_gWr);

    // instantiations + dynamic smem
    auto kWqk   = gemm_tc<128,128,64,32, 1, true , true , 0>;  // Wqk = Wq @ Wk^T
    auto kBig   = gemm_tc<128,128,64,32, 0, false, false, 0>;  // QV = x @ [Wqk|Wv]
    auto kGate  = gemm_tc< 64,128,32,32, 0, true , false, 0>;  // G = M @ gWr
    auto kScore = gemm_tc< 64, 64,32,32, 1, false, true , 0>;  // scores = Qk @ M^T
    auto kWrite = gemm_tc< 64,128,32,32, 2, false, false, 1>;  // M <- update(W^T@Vt)

    const int SM_WQK = 2*(128*36 + 128*36)*4;  // 73728
    const int SM_BIG = 2*(128*36 +  32*136)*4; // 71680
    const int SM_GAT = 2*( 64*36 +  32*136)*4; // 53248
    const int SM_SCO = 2*( 64*36 +  64*36 )*4; // 36864
    const int SM_WRT = 2*( 32*72 +  32*136)*4; // 53248

    cudaFuncSetAttribute(kWqk,   cudaFuncAttributeMaxDynamicSharedMemorySize, SM_WQK);
    cudaFuncSetAttribute(kBig,   cudaFuncAttributeMaxDynamicSharedMemorySize, SM_BIG);
    cudaFuncSetAttribute(kGate,  cudaFuncAttributeMaxDynamicSharedMemorySize, SM_GAT);
    cudaFuncSetAttribute(kScore, cudaFuncAttributeMaxDynamicSharedMemorySize, SM_SCO);
    cudaFuncSetAttribute(kWrite, cudaFuncAttributeMaxDynamicSharedMemorySize, SM_WRT);

    const long long sQV = (long long)T_*NW_;
    const long long sM  = (long long)S_*D_;
    const long long sWb = (long long)T_*S_;

    k_valid<<<B_, 512>>>(mask);
    k_embed<<<B_*T_, 192>>>(ids, tok, pos);
    k_minit<<<(B_*S_*D_ + 255)/256, 256>>>(mem);
    k_round<<<(D_*D_ + 255)/256, 256>>>(gW, pgWr, D_*D_);
    k_packWv<<<(D_*D_ + 255)/256, 256>>>(Wv);

    // Wqk = Wq @ Wk^T  (768x768x768, NT, both cvt) -> left half of g_Wp (ldc = 1536)
    kWqk<<<dim3(D_/128, D_/128, 1), 256, SM_WQK>>>(
        Wq, Wk, pWp, nullptr, nullptr, D_, D_, D_, D_, D_, NW_, 0,0,0);

    // QV = x @ [Wqk | Wv]  (16384 x 1536 x 768)
    kBig<<<dim3(NW_/128, (B_*T_)/128, 1), 256, SM_BIG>>>(
        px, pWp, pQV, nullptr, nullptr, B_*T_, NW_, D_, D_, NW_, NW_, 0,0,0);

    for (int step = 0; step < 4; step++) {
        // scores[b] = Qk[b] @ M[b]^T   (512 x 64, K=768)
        kScore<<<dim3(1, T_/64, B_), 128, SM_SCO>>>(
            pQV, pM, pW, nullptr, nullptr, T_, S_, D_, NW_, D_, S_, sQV, sM, sWb);
        k_softmax<<<(B_*T_)/8, 256>>>(mask);
        // G = M @ gate_W   (2048 x 768 x 768)
        kGate<<<dim3(D_/128, (B_*S_)/64, 1), 256, SM_GAT>>>(
            pM, pgWr, pG, nullptr, nullptr, B_*S_, D_, D_, D_, D_, D_, 0,0,0);
        // M <- clip(0.9M + 0.1 sigmoid(G+gb) * (W^T @ Vt))   (64 x 768, K=512)
        kWrite<<<dim3(D_/128, 1, B_), 256, SM_WRT>>>(
            pW, pQV + D_, pM, pG, gb, S_, D_, T_, S_, NW_, D_, sWb, sQV, sM);
    }

    // final read
    kScore<<<dim3(1, T_/64, B_), 128, SM_SCO>>>(
        pQV, pM, pW, nullptr, nullptr, T_, S_, D_, NW_, D_, S_, sQV, sM, sWb);
    k_softmax<<<(B_*T_)/8, 256>>>(mask);
    k_colsum<<<B_, S_>>>(mask);
    k_final<<<B_, 256>>>(lng, lnb, cW, cb, out);
}

// round 6
// speedup vs baseline: 6.2319x; 1.0366x over previous
#include <cuda_runtime.h>
#include <cstdint>
#include <math.h>

#define B_  32
#define T_  512
#define S_  64
#define D_  768
#define C_  8
#define NW_ 1536   // packed [Wqk | Wv] width

// ---------------- scratch (static device globals; allocation-free) ----------
__device__ float g_x  [B_*T_*D_];    // embedded input, tf32-rounded
__device__ float g_QV [B_*T_*NW_];   // cols 0..767 = Qk, 768..1535 = Vt
__device__ float g_M0 [B_*S_*D_];    // fp32 memory state (ping)
__device__ float g_M1 [B_*S_*D_];    // fp32 memory state (pong)
__device__ float g_W  [B_*T_*S_];    // softmax weights
__device__ float g_Wp [D_*NW_];      // packed [Wqk | Wv], tf32
__device__ float g_gWr[D_*D_];       // gate_W, tf32
__device__ float g_cw [B_*S_];
__device__ float g_valid[B_];

// ---------------- helpers ----------------------------------------------------
__device__ __forceinline__ float to_tf32(float f) {
    unsigned int u;
    asm("cvt.rna.tf32.f32 %0, %1;" : "=r"(u) : "f"(f));
    return __uint_as_float(u);
}

__device__ __forceinline__ void mma_tf32(float& c0, float& c1, float& c2, float& c3,
                                         float a0, float a1, float a2, float a3,
                                         float b0, float b1) {
    asm("mma.sync.aligned.m16n8k8.row.col.f32.tf32.tf32.f32 "
        "{%0,%1,%2,%3}, {%4,%5,%6,%7}, {%8,%9}, {%0,%1,%2,%3};"
        : "+f"(c0), "+f"(c1), "+f"(c2), "+f"(c3)
        : "r"(__float_as_uint(a0)), "r"(__float_as_uint(a1)),
          "r"(__float_as_uint(a2)), "r"(__float_as_uint(a3)),
          "r"(__float_as_uint(b0)), "r"(__float_as_uint(b1)));
}

__device__ __forceinline__ void cp_async16(float* dst, const float* src) {
    unsigned u = (unsigned)__cvta_generic_to_shared(dst);
    asm volatile("cp.async.cg.shared.global [%0], [%1], 16;" :: "r"(u), "l"(src));
}
#define CP_COMMIT() asm volatile("cp.async.commit_group;")
#define CP_WAIT1()  asm volatile("cp.async.wait_group 1;")
#define CP_WAIT0()  asm volatile("cp.async.wait_group 0;")

// ---------------- small kernels ---------------------------------------------
__global__ void k_valid(const int* __restrict__ mask) {
    __shared__ int sh[512];
    int b = blockIdx.x, t = threadIdx.x;
    sh[t] = (mask[b*T_ + t] > 0) ? 1 : 0;
    __syncthreads();
    for (int o = 256; o > 0; o >>= 1) {
        if (t < o) sh[t] += sh[t + o];
        __syncthreads();
    }
    if (t == 0) g_valid[b] = (float)sh[0];
}

__global__ void k_embed(const int* __restrict__ ids,
                        const float* __restrict__ tok,
                        const float* __restrict__ pos) {
    int bt = blockIdx.x;
    int t  = bt % T_;
    long id = ids[bt];
    const float4* te = (const float4*)(tok + id * (long)D_);
    const float4* pe = (const float4*)(pos + (long)t * D_);
    float4* xo = (float4*)(g_x + (long)bt * D_);
    int i = threadIdx.x;
    float4 a = te[i], p4 = pe[i];
    a.x = to_tf32(a.x + p4.x); a.y = to_tf32(a.y + p4.y);
    a.z = to_tf32(a.z + p4.z); a.w = to_tf32(a.w + p4.w);
    xo[i] = a;
}

__global__ void k_minit(const float* __restrict__ mem) {
    int i = blockIdx.x * blockDim.x + threadIdx.x;
    if (i < B_*S_*D_) g_M0[i] = mem[i % (S_*D_)];
}

__global__ void k_round(const float* __restrict__ src, float* __restrict__ dst, int n) {
    int i = blockIdx.x * blockDim.x + threadIdx.x;
    if (i < n) dst[i] = to_tf32(src[i]);
}

__global__ void k_packWv(const float* __restrict__ Wv) {
    int i = blockIdx.x * blockDim.x + threadIdx.x;
    if (i >= D_*D_) return;
    int k = i / D_, j = i % D_;
    g_Wp[(size_t)k*NW_ + D_ + j] = to_tf32(Wv[i]);
}

// ---------------- generic tf32 GEMM (for Wqk and the big QV projection) -----
// MODE 0 = NN, MODE 1 = NT (as before)
template<int BM, int BN, int WM, int WN, int MODE, bool CVT_A, bool CVT_B>
__global__ void __launch_bounds__((BM/WM)*(BN/WN)*32, 2)
gemm_tc(const float* __restrict__ Ag, const float* __restrict__ Bg, float* __restrict__ Cg,
        int M, int N, int K, int lda, int ldb, int ldc)
{
    constexpr int BK = 32;
    constexpr int WARPS   = (BM/WM)*(BN/WN);
    constexpr int THREADS = WARPS*32;
    constexpr int MA = WM/16;
    constexpr int NA = WN/8;
    constexpr int ALD = 36;
    constexpr int AE  = BM*ALD;
    constexpr int BLD = (MODE==1) ? 36 : (BN+8);
    constexpr int BE  = ((MODE==1) ? BN : BK)*BLD;

    extern __shared__ float smbuf[];
    float* Abuf = smbuf;
    float* Bbuf = smbuf + 2*AE;

    const float* A = Ag;
    const float* B = Bg;
    float*       C = Cg;

    const int tid    = threadIdx.x;
    const int warpId = tid >> 5;
    const int lane   = tid & 31;
    const int g      = lane >> 2;
    const int tig    = lane & 3;
    const int warp_m = (warpId % (BM/WM)) * WM;
    const int warp_n = (warpId / (BM/WM)) * WN;
    const int rowBase = blockIdx.y * BM;
    const int colBase = blockIdx.x * BN;

    float acc[MA][NA][4];
#pragma unroll
    for (int i = 0; i < MA; i++)
#pragma unroll
        for (int j = 0; j < NA; j++) {
            acc[i][j][0]=0.f; acc[i][j][1]=0.f; acc[i][j][2]=0.f; acc[i][j][3]=0.f;
        }

    auto load_tile = [&](int kt, int s) {
        const int k0 = kt * BK;
        float* As = Abuf + s*AE;
        float* Bs = Bbuf + s*BE;
#pragma unroll
        for (int idx = tid; idx < BM*8; idx += THREADS) {
            int r = idx >> 3, c = idx & 7;
            cp_async16(As + r*ALD + 4*c, A + (long long)(rowBase + r)*lda + k0 + 4*c);
        }
        if (MODE == 1) {
#pragma unroll
            for (int idx = tid; idx < BN*8; idx += THREADS) {
                int r = idx >> 3, c = idx & 7;
                cp_async16(Bs + r*BLD + 4*c, B + (long long)(colBase + r)*ldb + k0 + 4*c);
            }
        } else {
#pragma unroll
            for (int idx = tid; idx < BK*(BN/4); idx += THREADS) {
                int r = idx / (BN/4), c = idx % (BN/4);
                cp_async16(Bs + r*BLD + 4*c, B + (long long)(k0 + r)*ldb + colBase + 4*c);
            }
        }
    };

    const int KT = K / BK;
    load_tile(0, 0);
    CP_COMMIT();

    for (int kt = 0; kt < KT; kt++) {
        const int cur = kt & 1;
        if (kt + 1 < KT) load_tile(kt + 1, cur ^ 1);
        CP_COMMIT();
        CP_WAIT1();
        __syncthreads();

        const float* As = Abuf + cur*AE;
        const float* Bs = Bbuf + cur*BE;

#pragma unroll
        for (int ks = 0; ks < 4; ks++) {
            const int kk = 8*ks;
            float a[MA][4], bf[NA][2];
#pragma unroll
            for (int ma = 0; ma < MA; ma++) {
                int mb = warp_m + 16*ma + g;
                const float* p0 = As + mb*ALD;
                const float* p1 = As + (mb+8)*ALD;
                a[ma][0] = p0[kk+tig];   a[ma][1] = p1[kk+tig];
                a[ma][2] = p0[kk+tig+4]; a[ma][3] = p1[kk+tig+4];
            }
            if (CVT_A) {
#pragma unroll
                for (int ma = 0; ma < MA; ma++)
#pragma unroll
                    for (int j = 0; j < 4; j++) a[ma][j] = to_tf32(a[ma][j]);
            }
            if (MODE == 1) {
#pragma unroll
                for (int na = 0; na < NA; na++) {
                    const float* p = Bs + (warp_n + 8*na + g)*BLD;
                    bf[na][0] = p[kk+tig]; bf[na][1] = p[kk+tig+4];
                }
            } else {
                const float* q0 = Bs + (kk + tig    )*BLD;
                const float* q1 = Bs + (kk + tig + 4)*BLD;
#pragma unroll
                for (int na = 0; na < NA; na++) {
                    int nb = warp_n + 8*na + g;
                    bf[na][0] = q0[nb]; bf[na][1] = q1[nb];
                }
            }
            if (CVT_B) {
#pragma unroll
                for (int na = 0; na < NA; na++) {
                    bf[na][0] = to_tf32(bf[na][0]);
                    bf[na][1] = to_tf32(bf[na][1]);
                }
            }
#pragma unroll
            for (int ma = 0; ma < MA; ma++)
#pragma unroll
                for (int na = 0; na < NA; na++)
                    mma_tf32(acc[ma][na][0], acc[ma][na][1], acc[ma][na][2], acc[ma][na][3],
                             a[ma][0], a[ma][1], a[ma][2], a[ma][3],
                             bf[na][0], bf[na][1]);
        }
        __syncthreads();
    }

#pragma unroll
    for (int ma = 0; ma < MA; ma++) {
        int r0 = rowBase + warp_m + 16*ma + g;
        int r1 = r0 + 8;
#pragma unroll
        for (int na = 0; na < NA; na++) {
            int cc = colBase + warp_n + 8*na + 2*tig;
            *(float2*)(C + (long long)r0*ldc + cc) =
                make_float2(to_tf32(acc[ma][na][0]), to_tf32(acc[ma][na][1]));
            *(float2*)(C + (long long)r1*ldc + cc) =
                make_float2(to_tf32(acc[ma][na][2]), to_tf32(acc[ma][na][3]));
        }
    }
}

// ---------------- fused scores+softmax ---------------------------------------
// scores[b, t, s] = clip(Qk[b,t,:]·M[b,s,:] * scale); softmax over s; mask.
// BM=64 (t), BN=64 (s = all slots), 4 warps, warp tile 16x64 -> full rows per warp.
__global__ void __launch_bounds__(128)
k_score_softmax(const float* __restrict__ Qk, const float* __restrict__ Mc,
                float* __restrict__ Wout, const int* __restrict__ mask)
{
    constexpr int AE = 64*36;
    extern __shared__ float smbuf[];
    float* Abuf = smbuf;
    float* Bbuf = smbuf + 2*AE;

    const int b = blockIdx.z;
    const int rowBase = blockIdx.y * 64;
    const float* A  = Qk + (long long)b*T_*NW_;
    const float* Bm = Mc + (long long)b*S_*D_;

    const int tid  = threadIdx.x;
    const int w    = tid >> 5;
    const int lane = tid & 31;
    const int g    = lane >> 2;
    const int tig  = lane & 3;

    float acc[8][4];
#pragma unroll
    for (int j = 0; j < 8; j++) { acc[j][0]=0.f; acc[j][1]=0.f; acc[j][2]=0.f; acc[j][3]=0.f; }

    auto load_tile = [&](int kt, int s) {
        const int k0 = kt * 32;
        float* As = Abuf + s*AE;
        float* Bs = Bbuf + s*AE;
#pragma unroll
        for (int idx = tid; idx < 512; idx += 128) {
            int r = idx >> 3, c = idx & 7;
            cp_async16(As + r*36 + 4*c, A + (long long)(rowBase + r)*NW_ + k0 + 4*c);
        }
#pragma unroll
        for (int idx = tid; idx < 512; idx += 128) {
            int r = idx >> 3, c = idx & 7;
            cp_async16(Bs + r*36 + 4*c, Bm + (long long)r*D_ + k0 + 4*c);
        }
    };

    load_tile(0, 0);
    CP_COMMIT();
    for (int kt = 0; kt < 24; kt++) {
        const int cur = kt & 1;
        if (kt + 1 < 24) load_tile(kt + 1, cur ^ 1);
        CP_COMMIT();
        CP_WAIT1();
        __syncthreads();
        const float* As = Abuf + cur*AE;
        const float* Bs = Bbuf + cur*AE;
#pragma unroll
        for (int ks = 0; ks < 4; ks++) {
            const int kk = 8*ks;
            int mb = 16*w + g;
            const float* p0 = As + mb*36;
            const float* p1 = As + (mb+8)*36;
            float a0 = p0[kk+tig],   a1 = p1[kk+tig];
            float a2 = p0[kk+tig+4], a3 = p1[kk+tig+4];
            float bf[8][2];
#pragma unroll
            for (int na = 0; na < 8; na++) {
                const float* p = Bs + (8*na + g)*36;
                bf[na][0] = to_tf32(p[kk+tig]); bf[na][1] = to_tf32(p[kk+tig+4]);
            }
#pragma unroll
            for (int na = 0; na < 8; na++)
                mma_tf32(acc[na][0], acc[na][1], acc[na][2], acc[na][3],
                         a0, a1, a2, a3, bf[na][0], bf[na][1]);
        }
        __syncthreads();
    }

    // softmax epilogue: warp owns rows t0 = rowBase+16w+g and t1 = t0+8 fully.
    const float scale = 0.03608439182435161f;
    float mx0 = -1e30f, mx1 = -1e30f;
#pragma unroll
    for (int na = 0; na < 8; na++) {
#pragma unroll
        for (int j = 0; j < 4; j++) {
            float v = fminf(fmaxf(acc[na][j]*scale, -20.f), 20.f);
            acc[na][j] = v;
            if (j < 2) mx0 = fmaxf(mx0, v); else mx1 = fmaxf(mx1, v);
        }
    }
    mx0 = fmaxf(mx0, __shfl_xor_sync(0xffffffffu, mx0, 1));
    mx0 = fmaxf(mx0, __shfl_xor_sync(0xffffffffu, mx0, 2));
    mx1 = fmaxf(mx1, __shfl_xor_sync(0xffffffffu, mx1, 1));
    mx1 = fmaxf(mx1, __shfl_xor_sync(0xffffffffu, mx1, 2));
    float sm0 = 0.f, sm1 = 0.f;
#pragma unroll
    for (int na = 0; na < 8; na++) {
        acc[na][0] = expf(acc[na][0] - mx0); sm0 += acc[na][0];
        acc[na][1] = expf(acc[na][1] - mx0); sm0 += acc[na][1];
        acc[na][2] = expf(acc[na][2] - mx1); sm1 += acc[na][2];
        acc[na][3] = expf(acc[na][3] - mx1); sm1 += acc[na][3];
    }
    sm0 += __shfl_xor_sync(0xffffffffu, sm0, 1);
    sm0 += __shfl_xor_sync(0xffffffffu, sm0, 2);
    sm1 += __shfl_xor_sync(0xffffffffu, sm1, 1);
    sm1 += __shfl_xor_sync(0xffffffffu, sm1, 2);
    const int t0 = rowBase + 16*w + g;
    const int t1 = t0 + 8;
    float vf  = g_valid[b];
    float mf0 = (vf > 0.f) ? ((mask[b*T_ + t0] > 0) ? 1.f : 0.f) : 1.f;
    float mf1 = (vf > 0.f) ? ((mask[b*T_ + t1] > 0) ? 1.f : 0.f) : 1.f;
    float i0 = mf0 / sm0, i1 = mf1 / sm1;
    float* r0 = Wout + ((size_t)b*T_ + t0)*S_;
    float* r1 = Wout + ((size_t)b*T_ + t1)*S_;
#pragma unroll
    for (int na = 0; na < 8; na++) {
        int cc = 8*na + 2*tig;
        *(float2*)(r0 + cc) = make_float2(to_tf32(acc[na][0]*i0), to_tf32(acc[na][1]*i0));
        *(float2*)(r1 + cc) = make_float2(to_tf32(acc[na][2]*i1), to_tf32(acc[na][3]*i1));
    }
}

// ---------------- fused gate + write + memory update -------------------------
// accG = M @ gate_W (K=768, NN); accW = W^T @ Vt (K=512, TN);
// Mn = clip(0.9*Mc + 0.1*sigmoid(accG+gb)*accW). Output tile 64 x 128, 8 warps.
__global__ void __launch_bounds__(256)
k_gatewrite(const float* __restrict__ Mc, const float* __restrict__ gWr,
            const float* __restrict__ Wt, const float* __restrict__ Vtq,
            const float* __restrict__ gbp, float* __restrict__ Mn)
{
    constexpr int AE = 2304;           // phase1: 64*36 ; phase2: 32*72
    constexpr int BE = 32*136;         // 4352
    extern __shared__ float smbuf[];
    float* Abuf = smbuf;
    float* Bbuf = smbuf + 2*AE;

    const int b = blockIdx.z;
    const int colBase = blockIdx.x * 128;
    const float* Mp = Mc  + (long long)b*S_*D_;
    const float* Wp = Wt  + (long long)b*T_*S_;
    const float* Vp = Vtq + (long long)b*T_*NW_ + D_;

    const int tid  = threadIdx.x;
    const int wId  = tid >> 5;
    const int lane = tid & 31;
    const int g    = lane >> 2;
    const int tig  = lane & 3;
    const int warp_m = (wId & 1) * 32;
    const int warp_n = (wId >> 1) * 32;

    float accG[2][4][4], accW[2][4][4];
#pragma unroll
    for (int i = 0; i < 2; i++)
#pragma unroll
        for (int j = 0; j < 4; j++)
#pragma unroll
            for (int k = 0; k < 4; k++) { accG[i][j][k] = 0.f; accW[i][j][k] = 0.f; }

    // ---- phase 1: gate = M @ gWr, K = 768 ----
    auto loadG = [&](int kt, int s) {
        const int k0 = kt * 32;
        float* As = Abuf + s*AE;
        float* Bs = Bbuf + s*BE;
#pragma unroll
        for (int idx = tid; idx < 512; idx += 256) {
            int r = idx >> 3, c = idx & 7;
            cp_async16(As + r*36 + 4*c, Mp + (long long)r*D_ + k0 + 4*c);
        }
#pragma unroll
        for (int idx = tid; idx < 1024; idx += 256) {
            int r = idx >> 5, c = idx & 31;
            cp_async16(Bs + r*136 + 4*c, gWr + (long long)(k0 + r)*D_ + colBase + 4*c);
        }
    };
    loadG(0, 0);
    CP_COMMIT();
    for (int kt = 0; kt < 24; kt++) {
        const int cur = kt & 1;
        if (kt + 1 < 24) loadG(kt + 1, cur ^ 1);
        CP_COMMIT();
        CP_WAIT1();
        __syncthreads();
        const float* As = Abuf + cur*AE;
        const float* Bs = Bbuf + cur*BE;
#pragma unroll
        for (int ks = 0; ks < 4; ks++) {
            const int kk = 8*ks;
            float a[2][4], bf[4][2];
#pragma unroll
            for (int ma = 0; ma < 2; ma++) {
                int mb = warp_m + 16*ma + g;
                const float* p0 = As + mb*36;
                const float* p1 = As + (mb+8)*36;
                a[ma][0] = to_tf32(p0[kk+tig]);   a[ma][1] = to_tf32(p1[kk+tig]);
                a[ma][2] = to_tf32(p0[kk+tig+4]); a[ma][3] = to_tf32(p1[kk+tig+4]);
            }
            const float* q0 = Bs + (kk + tig    )*136;
            const float* q1 = Bs + (kk + tig + 4)*136;
#pragma unroll
            for (int na = 0; na < 4; na++) {
                int nb = warp_n + 8*na + g;
                bf[na][0] = q0[nb]; bf[na][1] = q1[nb];
            }
#pragma unroll
            for (int ma = 0; ma < 2; ma++)
#pragma unroll
                for (int na = 0; na < 4; na++)
                    mma_tf32(accG[ma][na][0], accG[ma][na][1], accG[ma][na][2], accG[ma][na][3],
                             a[ma][0], a[ma][1], a[ma][2], a[ma][3],
                             bf[na][0], bf[na][1]);
        }
        __syncthreads();
    }
    CP_WAIT0();
    __syncthreads();

    // ---- phase 2: write = W^T @ Vt, K = 512 ----
    auto loadW = [&](int kt, int s) {
        const int k0 = kt * 32;
        float* As = Abuf + s*AE;
        float* Bs = Bbuf + s*BE;
#pragma unroll
        for (int idx = tid; idx < 512; idx += 256) {
            int r = idx >> 4, c = idx & 15;
            cp_async16(As + r*72 + 4*c, Wp + (long long)(k0 + r)*S_ + 4*c);
        }
#pragma unroll
        for (int idx = tid; idx < 1024; idx += 256) {
            int r = idx >> 5, c = idx & 31;
            cp_async16(Bs + r*136 + 4*c, Vp + (long long)(k0 + r)*NW_ + colBase + 4*c);
        }
    };
    loadW(0, 0);
    CP_COMMIT();
    for (int kt = 0; kt < 16; kt++) {
        const int cur = kt & 1;
        if (kt + 1 < 16) loadW(kt + 1, cur ^ 1);
        CP_COMMIT();
        CP_WAIT1();
        __syncthreads();
        const float* As = Abuf + cur*AE;
        const float* Bs = Bbuf + cur*BE;
#pragma unroll
        for (int ks = 0; ks < 4; ks++) {
            const int kk = 8*ks;
            float a[2][4], bf[4][2];
            const float* r0 = As + (kk + tig    )*72;
            const float* r1 = As + (kk + tig + 4)*72;
#pragma unroll
            for (int ma = 0; ma < 2; ma++) {
                int mb = warp_m + 16*ma + g;
                a[ma][0] = r0[mb]; a[ma][1] = r0[mb+8];
                a[ma][2] = r1[mb]; a[ma][3] = r1[mb+8];
            }
            const float* q0 = Bs + (kk + tig    )*136;
            const float* q1 = Bs + (kk + tig + 4)*136;
#pragma unroll
            for (int na = 0; na < 4; na++) {
                int nb = warp_n + 8*na + g;
                bf[na][0] = q0[nb]; bf[na][1] = q1[nb];
            }
#pragma unroll
            for (int ma = 0; ma < 2; ma++)
#pragma unroll
                for (int na = 0; na < 4; na++)
                    mma_tf32(accW[ma][na][0], accW[ma][na][1], accW[ma][na][2], accW[ma][na][3],
                             a[ma][0], a[ma][1], a[ma][2], a[ma][3],
                             bf[na][0], bf[na][1]);
        }
        __syncthreads();
    }

    // ---- epilogue: M update ----
    float* Mo = Mn + (long long)b*S_*D_;
#pragma unroll
    for (int ma = 0; ma < 2; ma++) {
        int s0 = warp_m + 16*ma + g;
        int s1 = s0 + 8;
#pragma unroll
        for (int na = 0; na < 4; na++) {
            int cc = colBase + warp_n + 8*na + 2*tig;
            float2 gb2 = *(const float2*)(gbp + cc);
#pragma unroll
            for (int rr = 0; rr < 2; rr++) {
                int row = rr ? s1 : s0;
                float gx = accG[ma][na][2*rr]   + gb2.x;
                float gy = accG[ma][na][2*rr+1] + gb2.y;
                float sx = 1.f / (1.f + expf(-gx));
                float sy = 1.f / (1.f + expf(-gy));
                float2 mo = *(const float2*)(Mp + (long long)row*D_ + cc);
                float nx = fminf(fmaxf(0.9f*mo.x + 0.1f*sx*accW[ma][na][2*rr],   -50.f), 50.f);
                float ny = fminf(fmaxf(0.9f*mo.y + 0.1f*sy*accW[ma][na][2*rr+1], -50.f), 50.f);
                *(float2*)(Mo + (long long)row*D_ + cc) = make_float2(nx, ny);
            }
        }
    }
}

// ---------------- column sum of masked W over T ------------------------------
__global__ void k_colsum(const int* __restrict__ mask) {
    int b = blockIdx.x, s = threadIdx.x;
    const float* Wb = g_W + (size_t)b * T_ * S_;
    const int*   mb = mask + b * T_;
    float acc = 0.f;
    for (int t = 0; t < T_; t++)
        acc += (mb[t] > 0) ? Wb[t*S_ + s] : 0.f;
    g_cw[b*S_ + s] = acc;
}

// ---------------- pooled; LayerNorm; logits ----------------------------------
__global__ void k_final(const float* __restrict__ ln_g, const float* __restrict__ ln_b,
                        const float* __restrict__ cls_W, const float* __restrict__ cls_b,
                        float* __restrict__ out)
{
    __shared__ float cw[S_];
    __shared__ float p[D_];
    __shared__ float red[256];
    int b = blockIdx.x, tid = threadIdx.x;
    if (tid < S_) cw[tid] = g_cw[b*S_ + tid];
    __syncthreads();
    float invn = 1.f / fmaxf(g_valid[b], 1.f);
    for (int d = tid; d < D_; d += 256) {
        float acc = 0.f;
        const float* Mb = g_M0 + (size_t)b*S_*D_ + d;
#pragma unroll 8
        for (int s = 0; s < S_; s++) acc += cw[s] * Mb[s*D_];
        p[d] = acc * invn;
    }
    __syncthreads();
    float ls = 0.f;
    for (int d = tid; d < D_; d += 256) ls += p[d];
    red[tid] = ls; __syncthreads();
    for (int o = 128; o > 0; o >>= 1) { if (tid < o) red[tid] += red[tid + o]; __syncthreads(); }
    float mu = red[0] / D_;
    __syncthreads();
    float lv = 0.f;
    for (int d = tid; d < D_; d += 256) { float z = p[d] - mu; lv += z*z; }
    red[tid] = lv; __syncthreads();
    for (int o = 128; o > 0; o >>= 1) { if (tid < o) red[tid] += red[tid + o]; __syncthreads(); }
    float rs = rsqrtf(red[0] / D_ + 1e-5f);
    __syncthreads();
    for (int d = tid; d < D_; d += 256)
        p[d] = (p[d] - mu) * rs * ln_g[d] + ln_b[d];
    __syncthreads();
    int w = tid >> 5, lane = tid & 31;
    float acc = 0.f;
    for (int d = lane; d < D_; d += 32) acc += p[d] * cls_W[d*C_ + w];
#pragma unroll
    for (int o = 16; o > 0; o >>= 1) acc += __shfl_down_sync(0xffffffffu, acc, o);
    if (lane == 0) {
        float v = acc + cls_b[w];
        if (!isfinite(v)) v = 0.f;
        out[b*C_ + w] = v;
    }
}

// ---------------- launch -----------------------------------------------------
extern "C" void kernel_launch(void* const* d_in, const int* in_sizes, int n_in,
                              void* d_out, int out_size)
{
    const int*   ids  = (const int*)  d_in[0];
    const int*   mask = (const int*)  d_in[1];
    const float* tok  = (const float*)d_in[2];
    const float* pos  = (const float*)d_in[3];
    const float* Wq   = (const float*)d_in[4];
    const float* Wk   = (const float*)d_in[5];
    const float* Wv   = (const float*)d_in[6];
    const float* gW   = (const float*)d_in[7];
    const float* gb   = (const float*)d_in[8];
    const float* lng  = (const float*)d_in[9];
    const float* lnb  = (const float*)d_in[10];
    const float* cW   = (const float*)d_in[11];
    const float* cb   = (const float*)d_in[12];
    const float* mem  = (const float*)d_in[13];
    float* out = (float*)d_out;

    float *px, *pQV, *pM0, *pM1, *pW, *pWp, *pgWr;
    cudaGetSymbolAddress((void**)&px,   g_x);
    cudaGetSymbolAddress((void**)&pQV,  g_QV);
    cudaGetSymbolAddress((void**)&pM0,  g_M0);
    cudaGetSymbolAddress((void**)&pM1,  g_M1);
    cudaGetSymbolAddress((void**)&pW,   g_W);
    cudaGetSymbolAddress((void**)&pWp,  g_Wp);
    cudaGetSymbolAddress((void**)&pgWr, g_gWr);

    auto kWqk = gemm_tc<128,128,64,32, 1, true , true >;  // Wqk = Wq @ Wk^T
    auto kBig = gemm_tc<128,128,64,32, 0, false, false>;  // QV = x @ [Wqk|Wv]

    const int SM_WQK = 2*(128*36 + 128*36)*4;  // 73728
    const int SM_BIG = 2*(128*36 +  32*136)*4; // 71680
    const int SM_SCO = 4*(64*36)*4;            // 36864
    const int SM_GW  = (2*2304 + 2*4352)*4;    // 53248

    cudaFuncSetAttribute(kWqk, cudaFuncAttributeMaxDynamicSharedMemorySize, SM_WQK);
    cudaFuncSetAttribute(kBig, cudaFuncAttributeMaxDynamicSharedMemorySize, SM_BIG);
    cudaFuncSetAttribute(k_score_softmax, cudaFuncAttributeMaxDynamicSharedMemorySize, SM_SCO);
    cudaFuncSetAttribute(k_gatewrite,     cudaFuncAttributeMaxDynamicSharedMemorySize, SM_GW);

    k_valid<<<B_, 512>>>(mask);
    k_embed<<<B_*T_, 192>>>(ids, tok, pos);
    k_minit<<<(B_*S_*D_ + 255)/256, 256>>>(mem);
    k_round<<<(D_*D_ + 255)/256, 256>>>(gW, pgWr, D_*D_);
    k_packWv<<<(D_*D_ + 255)/256, 256>>>(Wv);

    // Wqk = Wq @ Wk^T -> left half of g_Wp (ldc = 1536)
    kWqk<<<dim3(D_/128, D_/128, 1), 256, SM_WQK>>>(Wq, Wk, pWp, D_, D_, D_, D_, D_, NW_);

    // QV = x @ [Wqk | Wv]  (16384 x 1536 x 768)
    kBig<<<dim3(NW_/128, (B_*T_)/128, 1), 256, SM_BIG>>>(px, pWp, pQV, B_*T_, NW_, D_, D_, NW_, NW_);

    float* Mbuf[2] = {pM0, pM1};
    for (int step = 0; step < 4; step++) {
        const float* Mc = Mbuf[step & 1];
        float*       Mn = Mbuf[(step & 1) ^ 1];
        k_score_softmax<<<dim3(1, T_/64, B_), 128, SM_SCO>>>(pQV, Mc, pW, mask);
        k_gatewrite<<<dim3(D_/128, 1, B_), 256, SM_GW>>>(Mc, pgWr, pW, pQV, gb, Mn);
    }
    // after 4 steps state is back in M0
    k_score_softmax<<<dim3(1, T_/64, B_), 128, SM_SCO>>>(pQV, pM0, pW, mask);
    k_colsum<<<B_, S_>>>(mask);
    k_final<<<B_, 256>>>(lng, lnb, cW, cb, out);
}

// round 7
// speedup vs baseline: 6.2734x; 1.0067x over previous
#include <cuda_runtime.h>
#include <cstdint>
#include <math.h>

#define B_  32
#define T_  512
#define S_  64
#define D_  768
#define C_  8
#define NW_ 1536   // packed [Wqk | Wv] width

// ---------------- scratch (static device globals; allocation-free) ----------
__device__ float g_x  [B_*T_*D_];    // embedded input, tf32-rounded
__device__ float g_QV [B_*T_*NW_];   // cols 0..767 = Qk, 768..1535 = Vt
__device__ float g_M0 [B_*S_*D_];    // fp32 memory state (ping)
__device__ float g_M1 [B_*S_*D_];    // fp32 memory state (pong)
__device__ float g_W  [B_*T_*S_];    // softmax weights
__device__ float g_Wp [D_*NW_];      // packed [Wqk | Wv], tf32
__device__ float g_gWr[D_*D_];       // gate_W, tf32
__device__ float g_cw [B_*S_];
__device__ float g_valid[B_];

// ---------------- helpers ----------------------------------------------------
__device__ __forceinline__ float to_tf32(float f) {
    unsigned int u;
    asm("cvt.rna.tf32.f32 %0, %1;" : "=r"(u) : "f"(f));
    return __uint_as_float(u);
}

__device__ __forceinline__ void mma_tf32(float& c0, float& c1, float& c2, float& c3,
                                         float a0, float a1, float a2, float a3,
                                         float b0, float b1) {
    asm("mma.sync.aligned.m16n8k8.row.col.f32.tf32.tf32.f32 "
        "{%0,%1,%2,%3}, {%4,%5,%6,%7}, {%8,%9}, {%0,%1,%2,%3};"
        : "+f"(c0), "+f"(c1), "+f"(c2), "+f"(c3)
        : "r"(__float_as_uint(a0)), "r"(__float_as_uint(a1)),
          "r"(__float_as_uint(a2)), "r"(__float_as_uint(a3)),
          "r"(__float_as_uint(b0)), "r"(__float_as_uint(b1)));
}

__device__ __forceinline__ void cp_async16(float* dst, const float* src) {
    unsigned u = (unsigned)__cvta_generic_to_shared(dst);
    asm volatile("cp.async.cg.shared.global [%0], [%1], 16;" :: "r"(u), "l"(src));
}
#define CP_COMMIT() asm volatile("cp.async.commit_group;")
#define CP_WAIT0()  asm volatile("cp.async.wait_group 0;")
template<int N> __device__ __forceinline__ void cp_wait() {
    asm volatile("cp.async.wait_group %0;" :: "n"(N));
}

// ---------------- small kernels ---------------------------------------------
__global__ void k_valid(const int* __restrict__ mask) {
    __shared__ int sh[512];
    int b = blockIdx.x, t = threadIdx.x;
    sh[t] = (mask[b*T_ + t] > 0) ? 1 : 0;
    __syncthreads();
    for (int o = 256; o > 0; o >>= 1) {
        if (t < o) sh[t] += sh[t + o];
        __syncthreads();
    }
    if (t == 0) g_valid[b] = (float)sh[0];
}

__global__ void k_embed(const int* __restrict__ ids,
                        const float* __restrict__ tok,
                        const float* __restrict__ pos) {
    int bt = blockIdx.x;
    int t  = bt % T_;
    long id = ids[bt];
    const float4* te = (const float4*)(tok + id * (long)D_);
    const float4* pe = (const float4*)(pos + (long)t * D_);
    float4* xo = (float4*)(g_x + (long)bt * D_);
    int i = threadIdx.x;
    float4 a = te[i], p4 = pe[i];
    a.x = to_tf32(a.x + p4.x); a.y = to_tf32(a.y + p4.y);
    a.z = to_tf32(a.z + p4.z); a.w = to_tf32(a.w + p4.w);
    xo[i] = a;
}

__global__ void k_minit(const float* __restrict__ mem) {
    int i = blockIdx.x * blockDim.x + threadIdx.x;
    if (i < B_*S_*D_) g_M0[i] = mem[i % (S_*D_)];
}

__global__ void k_round(const float* __restrict__ src, float* __restrict__ dst, int n) {
    int i = blockIdx.x * blockDim.x + threadIdx.x;
    if (i < n) dst[i] = to_tf32(src[i]);
}

__global__ void k_packWv(const float* __restrict__ Wv) {
    int i = blockIdx.x * blockDim.x + threadIdx.x;
    if (i >= D_*D_) return;
    int k = i / D_, j = i % D_;
    g_Wp[(size_t)k*NW_ + D_ + j] = to_tf32(Wv[i]);
}

// ---------------- generic tf32 GEMM, multistage cp.async ---------------------
// MODE 0 = NN, MODE 1 = NT
template<int BM, int BN, int WM, int WN, int MODE, bool CVT_A, bool CVT_B, int NST>
__global__ void __launch_bounds__((BM/WM)*(BN/WN)*32)
gemm_tc(const float* __restrict__ Ag, const float* __restrict__ Bg, float* __restrict__ Cg,
        int M, int N, int K, int lda, int ldb, int ldc)
{
    constexpr int BK = 32;
    constexpr int WARPS   = (BM/WM)*(BN/WN);
    constexpr int THREADS = WARPS*32;
    constexpr int MA = WM/16;
    constexpr int NA = WN/8;
    constexpr int ALD = 36;
    constexpr int AE  = BM*ALD;
    constexpr int BLD = (MODE==1) ? 36 : (BN+8);
    constexpr int BE  = ((MODE==1) ? BN : BK)*BLD;

    extern __shared__ float smbuf[];
    float* Abuf = smbuf;
    float* Bbuf = smbuf + NST*AE;

    const float* A = Ag;
    const float* B = Bg;
    float*       C = Cg;

    const int tid    = threadIdx.x;
    const int warpId = tid >> 5;
    const int lane   = tid & 31;
    const int g      = lane >> 2;
    const int tig    = lane & 3;
    const int warp_m = (warpId % (BM/WM)) * WM;
    const int warp_n = (warpId / (BM/WM)) * WN;
    const int rowBase = blockIdx.y * BM;
    const int colBase = blockIdx.x * BN;

    float acc[MA][NA][4];
#pragma unroll
    for (int i = 0; i < MA; i++)
#pragma unroll
        for (int j = 0; j < NA; j++) {
            acc[i][j][0]=0.f; acc[i][j][1]=0.f; acc[i][j][2]=0.f; acc[i][j][3]=0.f;
        }

    auto load_tile = [&](int kt, int s) {
        const int k0 = kt * BK;
        float* As = Abuf + s*AE;
        float* Bs = Bbuf + s*BE;
#pragma unroll
        for (int idx = tid; idx < BM*8; idx += THREADS) {
            int r = idx >> 3, c = idx & 7;
            cp_async16(As + r*ALD + 4*c, A + (long long)(rowBase + r)*lda + k0 + 4*c);
        }
        if (MODE == 1) {
#pragma unroll
            for (int idx = tid; idx < BN*8; idx += THREADS) {
                int r = idx >> 3, c = idx & 7;
                cp_async16(Bs + r*BLD + 4*c, B + (long long)(colBase + r)*ldb + k0 + 4*c);
            }
        } else {
#pragma unroll
            for (int idx = tid; idx < BK*(BN/4); idx += THREADS) {
                int r = idx / (BN/4), c = idx % (BN/4);
                cp_async16(Bs + r*BLD + 4*c, B + (long long)(k0 + r)*ldb + colBase + 4*c);
            }
        }
    };

    const int KT = K / BK;
#pragma unroll
    for (int s = 0; s < NST-1; s++) {
        if (s < KT) load_tile(s, s);
        CP_COMMIT();
    }

    for (int kt = 0; kt < KT; kt++) {
        const int pf = kt + NST - 1;
        if (pf < KT) load_tile(pf, pf % NST);
        CP_COMMIT();
        cp_wait<NST-2>();
        __syncthreads();

        const int cur = kt % NST;
        const float* As = Abuf + cur*AE;
        const float* Bs = Bbuf + cur*BE;

#pragma unroll
        for (int ks = 0; ks < 4; ks++) {
            const int kk = 8*ks;
            float a[MA][4], bf[NA][2];
#pragma unroll
            for (int ma = 0; ma < MA; ma++) {
                int mb = warp_m + 16*ma + g;
                const float* p0 = As + mb*ALD;
                const float* p1 = As + (mb+8)*ALD;
                a[ma][0] = p0[kk+tig];   a[ma][1] = p1[kk+tig];
                a[ma][2] = p0[kk+tig+4]; a[ma][3] = p1[kk+tig+4];
            }
            if (CVT_A) {
#pragma unroll
                for (int ma = 0; ma < MA; ma++)
#pragma unroll
                    for (int j = 0; j < 4; j++) a[ma][j] = to_tf32(a[ma][j]);
            }
            if (MODE == 1) {
#pragma unroll
                for (int na = 0; na < NA; na++) {
                    const float* p = Bs + (warp_n + 8*na + g)*BLD;
                    bf[na][0] = p[kk+tig]; bf[na][1] = p[kk+tig+4];
                }
            } else {
                const float* q0 = Bs + (kk + tig    )*BLD;
                const float* q1 = Bs + (kk + tig + 4)*BLD;
#pragma unroll
                for (int na = 0; na < NA; na++) {
                    int nb = warp_n + 8*na + g;
                    bf[na][0] = q0[nb]; bf[na][1] = q1[nb];
                }
            }
            if (CVT_B) {
#pragma unroll
                for (int na = 0; na < NA; na++) {
                    bf[na][0] = to_tf32(bf[na][0]);
                    bf[na][1] = to_tf32(bf[na][1]);
                }
            }
#pragma unroll
            for (int ma = 0; ma < MA; ma++)
#pragma unroll
                for (int na = 0; na < NA; na++)
                    mma_tf32(acc[ma][na][0], acc[ma][na][1], acc[ma][na][2], acc[ma][na][3],
                             a[ma][0], a[ma][1], a[ma][2], a[ma][3],
                             bf[na][0], bf[na][1]);
        }
        __syncthreads();
    }

#pragma unroll
    for (int ma = 0; ma < MA; ma++) {
        int r0 = rowBase + warp_m + 16*ma + g;
        int r1 = r0 + 8;
#pragma unroll
        for (int na = 0; na < NA; na++) {
            int cc = colBase + warp_n + 8*na + 2*tig;
            *(float2*)(C + (long long)r0*ldc + cc) =
                make_float2(to_tf32(acc[ma][na][0]), to_tf32(acc[ma][na][1]));
            *(float2*)(C + (long long)r1*ldc + cc) =
                make_float2(to_tf32(acc[ma][na][2]), to_tf32(acc[ma][na][3]));
        }
    }
}

// ---------------- fused scores+softmax (4-stage pipeline) --------------------
#define SCO_NST 4
__global__ void __launch_bounds__(128)
k_score_softmax(const float* __restrict__ Qk, const float* __restrict__ Mc,
                float* __restrict__ Wout, const int* __restrict__ mask)
{
    constexpr int AE = 64*36;
    extern __shared__ float smbuf[];
    float* Abuf = smbuf;
    float* Bbuf = smbuf + SCO_NST*AE;

    const int b = blockIdx.z;
    const int rowBase = blockIdx.y * 64;
    const float* A  = Qk + (long long)b*T_*NW_;
    const float* Bm = Mc + (long long)b*S_*D_;

    const int tid  = threadIdx.x;
    const int w    = tid >> 5;
    const int lane = tid & 31;
    const int g    = lane >> 2;
    const int tig  = lane & 3;

    float acc[8][4];
#pragma unroll
    for (int j = 0; j < 8; j++) { acc[j][0]=0.f; acc[j][1]=0.f; acc[j][2]=0.f; acc[j][3]=0.f; }

    auto load_tile = [&](int kt, int s) {
        const int k0 = kt * 32;
        float* As = Abuf + s*AE;
        float* Bs = Bbuf + s*AE;
#pragma unroll
        for (int idx = tid; idx < 512; idx += 128) {
            int r = idx >> 3, c = idx & 7;
            cp_async16(As + r*36 + 4*c, A + (long long)(rowBase + r)*NW_ + k0 + 4*c);
        }
#pragma unroll
        for (int idx = tid; idx < 512; idx += 128) {
            int r = idx >> 3, c = idx & 7;
            cp_async16(Bs + r*36 + 4*c, Bm + (long long)r*D_ + k0 + 4*c);
        }
    };

#pragma unroll
    for (int s = 0; s < SCO_NST-1; s++) { load_tile(s, s); CP_COMMIT(); }

    for (int kt = 0; kt < 24; kt++) {
        const int pf = kt + SCO_NST - 1;
        if (pf < 24) load_tile(pf, pf % SCO_NST);
        CP_COMMIT();
        cp_wait<SCO_NST-2>();
        __syncthreads();
        const int cur = kt % SCO_NST;
        const float* As = Abuf + cur*AE;
        const float* Bs = Bbuf + cur*AE;
#pragma unroll
        for (int ks = 0; ks < 4; ks++) {
            const int kk = 8*ks;
            int mb = 16*w + g;
            const float* p0 = As + mb*36;
            const float* p1 = As + (mb+8)*36;
            float a0 = p0[kk+tig],   a1 = p1[kk+tig];
            float a2 = p0[kk+tig+4], a3 = p1[kk+tig+4];
            float bf[8][2];
#pragma unroll
            for (int na = 0; na < 8; na++) {
                const float* p = Bs + (8*na + g)*36;
                bf[na][0] = to_tf32(p[kk+tig]); bf[na][1] = to_tf32(p[kk+tig+4]);
            }
#pragma unroll
            for (int na = 0; na < 8; na++)
                mma_tf32(acc[na][0], acc[na][1], acc[na][2], acc[na][3],
                         a0, a1, a2, a3, bf[na][0], bf[na][1]);
        }
        __syncthreads();
    }

    // softmax epilogue: warp owns full rows t0 = rowBase+16w+g and t1 = t0+8.
    const float scale = 0.03608439182435161f;
    float mx0 = -1e30f, mx1 = -1e30f;
#pragma unroll
    for (int na = 0; na < 8; na++) {
#pragma unroll
        for (int j = 0; j < 4; j++) {
            float v = fminf(fmaxf(acc[na][j]*scale, -20.f), 20.f);
            acc[na][j] = v;
            if (j < 2) mx0 = fmaxf(mx0, v); else mx1 = fmaxf(mx1, v);
        }
    }
    mx0 = fmaxf(mx0, __shfl_xor_sync(0xffffffffu, mx0, 1));
    mx0 = fmaxf(mx0, __shfl_xor_sync(0xffffffffu, mx0, 2));
    mx1 = fmaxf(mx1, __shfl_xor_sync(0xffffffffu, mx1, 1));
    mx1 = fmaxf(mx1, __shfl_xor_sync(0xffffffffu, mx1, 2));
    float sm0 = 0.f, sm1 = 0.f;
#pragma unroll
    for (int na = 0; na < 8; na++) {
        acc[na][0] = expf(acc[na][0] - mx0); sm0 += acc[na][0];
        acc[na][1] = expf(acc[na][1] - mx0); sm0 += acc[na][1];
        acc[na][2] = expf(acc[na][2] - mx1); sm1 += acc[na][2];
        acc[na][3] = expf(acc[na][3] - mx1); sm1 += acc[na][3];
    }
    sm0 += __shfl_xor_sync(0xffffffffu, sm0, 1);
    sm0 += __shfl_xor_sync(0xffffffffu, sm0, 2);
    sm1 += __shfl_xor_sync(0xffffffffu, sm1, 1);
    sm1 += __shfl_xor_sync(0xffffffffu, sm1, 2);
    const int t0 = rowBase + 16*w + g;
    const int t1 = t0 + 8;
    float vf  = g_valid[b];
    float mf0 = (vf > 0.f) ? ((mask[b*T_ + t0] > 0) ? 1.f : 0.f) : 1.f;
    float mf1 = (vf > 0.f) ? ((mask[b*T_ + t1] > 0) ? 1.f : 0.f) : 1.f;
    float i0 = mf0 / sm0, i1 = mf1 / sm1;
    float* r0 = Wout + ((size_t)b*T_ + t0)*S_;
    float* r1 = Wout + ((size_t)b*T_ + t1)*S_;
#pragma unroll
    for (int na = 0; na < 8; na++) {
        int cc = 8*na + 2*tig;
        *(float2*)(r0 + cc) = make_float2(to_tf32(acc[na][0]*i0), to_tf32(acc[na][1]*i0));
        *(float2*)(r1 + cc) = make_float2(to_tf32(acc[na][2]*i1), to_tf32(acc[na][3]*i1));
    }
}

// ---------------- fused gate + write + memory update (3-stage) ---------------
#define GW_NST 3
__global__ void __launch_bounds__(256)
k_gatewrite(const float* __restrict__ Mc, const float* __restrict__ gWr,
            const float* __restrict__ Wt, const float* __restrict__ Vtq,
            const float* __restrict__ gbp, float* __restrict__ Mn)
{
    constexpr int AE = 2304;           // phase1: 64*36 ; phase2: 32*72
    constexpr int BE = 32*136;         // 4352
    extern __shared__ float smbuf[];
    float* Abuf = smbuf;
    float* Bbuf = smbuf + GW_NST*AE;

    const int b = blockIdx.z;
    const int colBase = blockIdx.x * 128;
    const float* Mp = Mc  + (long long)b*S_*D_;
    const float* Wp = Wt  + (long long)b*T_*S_;
    const float* Vp = Vtq + (long long)b*T_*NW_ + D_;

    const int tid  = threadIdx.x;
    const int wId  = tid >> 5;
    const int lane = tid & 31;
    const int g    = lane >> 2;
    const int tig  = lane & 3;
    const int warp_m = (wId & 1) * 32;
    const int warp_n = (wId >> 1) * 32;

    float accG[2][4][4], accW[2][4][4];
#pragma unroll
    for (int i = 0; i < 2; i++)
#pragma unroll
        for (int j = 0; j < 4; j++)
#pragma unroll
            for (int k = 0; k < 4; k++) { accG[i][j][k] = 0.f; accW[i][j][k] = 0.f; }

    // ---- phase 1: gate = M @ gWr, K = 768 ----
    auto loadG = [&](int kt, int s) {
        const int k0 = kt * 32;
        float* As = Abuf + s*AE;
        float* Bs = Bbuf + s*BE;
#pragma unroll
        for (int idx = tid; idx < 512; idx += 256) {
            int r = idx >> 3, c = idx & 7;
            cp_async16(As + r*36 + 4*c, Mp + (long long)r*D_ + k0 + 4*c);
        }
#pragma unroll
        for (int idx = tid; idx < 1024; idx += 256) {
            int r = idx >> 5, c = idx & 31;
            cp_async16(Bs + r*136 + 4*c, gWr + (long long)(k0 + r)*D_ + colBase + 4*c);
        }
    };
#pragma unroll
    for (int s = 0; s < GW_NST-1; s++) { loadG(s, s); CP_COMMIT(); }
    for (int kt = 0; kt < 24; kt++) {
        const int pf = kt + GW_NST - 1;
        if (pf < 24) loadG(pf, pf % GW_NST);
        CP_COMMIT();
        cp_wait<GW_NST-2>();
        __syncthreads();
        const int cur = kt % GW_NST;
        const float* As = Abuf + cur*AE;
        const float* Bs = Bbuf + cur*BE;
#pragma unroll
        for (int ks = 0; ks < 4; ks++) {
            const int kk = 8*ks;
            float a[2][4], bf[4][2];
#pragma unroll
            for (int ma = 0; ma < 2; ma++) {
                int mb = warp_m + 16*ma + g;
                const float* p0 = As + mb*36;
                const float* p1 = As + (mb+8)*36;
                a[ma][0] = to_tf32(p0[kk+tig]);   a[ma][1] = to_tf32(p1[kk+tig]);
                a[ma][2] = to_tf32(p0[kk+tig+4]); a[ma][3] = to_tf32(p1[kk+tig+4]);
            }
            const float* q0 = Bs + (kk + tig    )*136;
            const float* q1 = Bs + (kk + tig + 4)*136;
#pragma unroll
            for (int na = 0; na < 4; na++) {
                int nb = warp_n + 8*na + g;
                bf[na][0] = q0[nb]; bf[na][1] = q1[nb];
            }
#pragma unroll
            for (int ma = 0; ma < 2; ma++)
#pragma unroll
                for (int na = 0; na < 4; na++)
                    mma_tf32(accG[ma][na][0], accG[ma][na][1], accG[ma][na][2], accG[ma][na][3],
                             a[ma][0], a[ma][1], a[ma][2], a[ma][3],
                             bf[na][0], bf[na][1]);
        }
        __syncthreads();
    }
    CP_WAIT0();
    __syncthreads();

    // ---- phase 2: write = W^T @ Vt, K = 512 ----
    auto loadW = [&](int kt, int s) {
        const int k0 = kt * 32;
        float* As = Abuf + s*AE;
        float* Bs = Bbuf + s*BE;
#pragma unroll
        for (int idx = tid; idx < 512; idx += 256) {
            int r = idx >> 4, c = idx & 15;
            cp_async16(As + r*72 + 4*c, Wp + (long long)(k0 + r)*S_ + 4*c);
        }
#pragma unroll
        for (int idx = tid; idx < 1024; idx += 256) {
            int r = idx >> 5, c = idx & 31;
            cp_async16(Bs + r*136 + 4*c, Vp + (long long)(k0 + r)*NW_ + colBase + 4*c);
        }
    };
#pragma unroll
    for (int s = 0; s < GW_NST-1; s++) { loadW(s, s); CP_COMMIT(); }
    for (int kt = 0; kt < 16; kt++) {
        const int pf = kt + GW_NST - 1;
        if (pf < 16) loadW(pf, pf % GW_NST);
        CP_COMMIT();
        cp_wait<GW_NST-2>();
        __syncthreads();
        const int cur = kt % GW_NST;
        const float* As = Abuf + cur*AE;
        const float* Bs = Bbuf + cur*BE;
#pragma unroll
        for (int ks = 0; ks < 4; ks++) {
            const int kk = 8*ks;
            float a[2][4], bf[4][2];
            const float* r0 = As + (kk + tig    )*72;
            const float* r1 = As + (kk + tig + 4)*72;
#pragma unroll
            for (int ma = 0; ma < 2; ma++) {
                int mb = warp_m + 16*ma + g;
                a[ma][0] = r0[mb]; a[ma][1] = r0[mb+8];
                a[ma][2] = r1[mb]; a[ma][3] = r1[mb+8];
            }
            const float* q0 = Bs + (kk + tig    )*136;
            const float* q1 = Bs + (kk + tig + 4)*136;
#pragma unroll
            for (int na = 0; na < 4; na++) {
                int nb = warp_n + 8*na + g;
                bf[na][0] = q0[nb]; bf[na][1] = q1[nb];
            }
#pragma unroll
            for (int ma = 0; ma < 2; ma++)
#pragma unroll
                for (int na = 0; na < 4; na++)
                    mma_tf32(accW[ma][na][0], accW[ma][na][1], accW[ma][na][2], accW[ma][na][3],
                             a[ma][0], a[ma][1], a[ma][2], a[ma][3],
                             bf[na][0], bf[na][1]);
        }
        __syncthreads();
    }

    // ---- epilogue: M update ----
    float* Mo = Mn + (long long)b*S_*D_;
#pragma unroll
    for (int ma = 0; ma < 2; ma++) {
        int s0 = warp_m + 16*ma + g;
        int s1 = s0 + 8;
#pragma unroll
        for (int na = 0; na < 4; na++) {
            int cc = colBase + warp_n + 8*na + 2*tig;
            float2 gb2 = *(const float2*)(gbp + cc);
#pragma unroll
            for (int rr = 0; rr < 2; rr++) {
                int row = rr ? s1 : s0;
                float gx = accG[ma][na][2*rr]   + gb2.x;
                float gy = accG[ma][na][2*rr+1] + gb2.y;
                float sx = 1.f / (1.f + expf(-gx));
                float sy = 1.f / (1.f + expf(-gy));
                float2 mo = *(const float2*)(Mp + (long long)row*D_ + cc);
                float nx = fminf(fmaxf(0.9f*mo.x + 0.1f*sx*accW[ma][na][2*rr],   -50.f), 50.f);
                float ny = fminf(fmaxf(0.9f*mo.y + 0.1f*sy*accW[ma][na][2*rr+1], -50.f), 50.f);
                *(float2*)(Mo + (long long)row*D_ + cc) = make_float2(nx, ny);
            }
        }
    }
}

// ---------------- column sum of masked W over T (parallel over T chunks) -----
__global__ void k_colsum(const int* __restrict__ mask) {
    __shared__ float red[4][S_];
    int b = blockIdx.x;
    int s = threadIdx.x & 63;
    int ch = threadIdx.x >> 6;          // 0..3
    const float* Wb = g_W + (size_t)b * T_ * S_;
    const int*   mb = mask + b * T_;
    float acc = 0.f;
    for (int t = ch*128; t < (ch+1)*128; t++)
        acc += (mb[t] > 0) ? Wb[t*S_ + s] : 0.f;
    red[ch][s] = acc;
    __syncthreads();
    if (ch == 0) g_cw[b*S_ + s] = red[0][s] + red[1][s] + red[2][s] + red[3][s];
}

// ---------------- pooled; LayerNorm; logits ----------------------------------
__global__ void k_final(const float* __restrict__ ln_g, const float* __restrict__ ln_b,
                        const float* __restrict__ cls_W, const float* __restrict__ cls_b,
                        float* __restrict__ out)
{
    __shared__ float cw[S_];
    __shared__ float p[D_];
    __shared__ float red[256];
    int b = blockIdx.x, tid = threadIdx.x;
    if (tid < S_) cw[tid] = g_cw[b*S_ + tid];
    __syncthreads();
    float invn = 1.f / fmaxf(g_valid[b], 1.f);
    for (int d = tid; d < D_; d += 256) {
        float acc = 0.f;
        const float* Mb = g_M0 + (size_t)b*S_*D_ + d;
#pragma unroll 8
        for (int s = 0; s < S_; s++) acc += cw[s] * Mb[s*D_];
        p[d] = acc * invn;
    }
    __syncthreads();
    float ls = 0.f;
    for (int d = tid; d < D_; d += 256) ls += p[d];
    red[tid] = ls; __syncthreads();
    for (int o = 128; o > 0; o >>= 1) { if (tid < o) red[tid] += red[tid + o]; __syncthreads(); }
    float mu = red[0] / D_;
    __syncthreads();
    float lv = 0.f;
    for (int d = tid; d < D_; d += 256) { float z = p[d] - mu; lv += z*z; }
    red[tid] = lv; __syncthreads();
    for (int o = 128; o > 0; o >>= 1) { if (tid < o) red[tid] += red[tid + o]; __syncthreads(); }
    float rs = rsqrtf(red[0] / D_ + 1e-5f);
    __syncthreads();
    for (int d = tid; d < D_; d += 256)
        p[d] = (p[d] - mu) * rs * ln_g[d] + ln_b[d];
    __syncthreads();
    int w = tid >> 5, lane = tid & 31;
    float acc = 0.f;
    for (int d = lane; d < D_; d += 32) acc += p[d] * cls_W[d*C_ + w];
#pragma unroll
    for (int o = 16; o > 0; o >>= 1) acc += __shfl_down_sync(0xffffffffu, acc, o);
    if (lane == 0) {
        float v = acc + cls_b[w];
        if (!isfinite(v)) v = 0.f;
        out[b*C_ + w] = v;
    }
}

// ---------------- launch -----------------------------------------------------
extern "C" void kernel_launch(void* const* d_in, const int* in_sizes, int n_in,
                              void* d_out, int out_size)
{
    const int*   ids  = (const int*)  d_in[0];
    const int*   mask = (const int*)  d_in[1];
    const float* tok  = (const float*)d_in[2];
    const float* pos  = (const float*)d_in[3];
    const float* Wq   = (const float*)d_in[4];
    const float* Wk   = (const float*)d_in[5];
    const float* Wv   = (const float*)d_in[6];
    const float* gW   = (const float*)d_in[7];
    const float* gb   = (const float*)d_in[8];
    const float* lng  = (const float*)d_in[9];
    const float* lnb  = (const float*)d_in[10];
    const float* cW   = (const float*)d_in[11];
    const float* cb   = (const float*)d_in[12];
    const float* mem  = (const float*)d_in[13];
    float* out = (float*)d_out;

    float *px, *pQV, *pM0, *pM1, *pW, *pWp, *pgWr;
    cudaGetSymbolAddress((void**)&px,   g_x);
    cudaGetSymbolAddress((void**)&pQV,  g_QV);
    cudaGetSymbolAddress((void**)&pM0,  g_M0);
    cudaGetSymbolAddress((void**)&pM1,  g_M1);
    cudaGetSymbolAddress((void**)&pW,   g_W);
    cudaGetSymbolAddress((void**)&pWp,  g_Wp);
    cudaGetSymbolAddress((void**)&pgWr, g_gWr);

    auto kWqk = gemm_tc<128,128,64,32, 1, true , true , 3>;  // Wqk = Wq @ Wk^T
    auto kBig = gemm_tc<128,128,64,32, 0, false, false, 3>;  // QV = x @ [Wqk|Wv]

    const int SM_WQK = 3*(128*36 + 128*36)*4;  // 110592
    const int SM_BIG = 3*(128*36 +  32*136)*4; // 107520
    const int SM_SCO = SCO_NST*2*(64*36)*4;    // 73728
    const int SM_GW  = GW_NST*(2304 + 4352)*4; // 79872

    cudaFuncSetAttribute(kWqk, cudaFuncAttributeMaxDynamicSharedMemorySize, SM_WQK);
    cudaFuncSetAttribute(kBig, cudaFuncAttributeMaxDynamicSharedMemorySize, SM_BIG);
    cudaFuncSetAttribute(k_score_softmax, cudaFuncAttributeMaxDynamicSharedMemorySize, SM_SCO);
    cudaFuncSetAttribute(k_gatewrite,     cudaFuncAttributeMaxDynamicSharedMemorySize, SM_GW);

    k_valid<<<B_, 512>>>(mask);
    k_embed<<<B_*T_, 192>>>(ids, tok, pos);
    k_minit<<<(B_*S_*D_ + 255)/256, 256>>>(mem);
    k_round<<<(D_*D_ + 255)/256, 256>>>(gW, pgWr, D_*D_);
    k_packWv<<<(D_*D_ + 255)/256, 256>>>(Wv);

    // Wqk = Wq @ Wk^T -> left half of g_Wp (ldc = 1536)
    kWqk<<<dim3(D_/128, D_/128, 1), 256, SM_WQK>>>(Wq, Wk, pWp, D_, D_, D_, D_, D_, NW_);

    // QV = x @ [Wqk | Wv]  (16384 x 1536 x 768)
    kBig<<<dim3(NW_/128, (B_*T_)/128, 1), 256, SM_BIG>>>(px, pWp, pQV, B_*T_, NW_, D_, D_, NW_, NW_);

    float* Mbuf[2] = {pM0, pM1};
    for (int step = 0; step < 4; step++) {
        const float* Mc = Mbuf[step & 1];
        float*       Mn = Mbuf[(step & 1) ^ 1];
        k_score_softmax<<<dim3(1, T_/64, B_), 128, SM_SCO>>>(pQV, Mc, pW, mask);
        k_gatewrite<<<dim3(D_/128, 1, B_), 256, SM_GW>>>(Mc, pgWr, pW, pQV, gb, Mn);
    }
    // after 4 steps state is back in M0
    k_score_softmax<<<dim3(1, T_/64, B_), 128, SM_SCO>>>(pQV, pM0, pW, mask);
    k_colsum<<<B_, 256>>>(mask);
    k_final<<<B_, 256>>>(lng, lnb, cW, cb, out);
}